// round 1
// baseline (speedup 1.0000x reference)
#include <cuda_runtime.h>
#include <math.h>

#define Bb 4
#define Ss 2048
#define Dd 1024
#define Hh 16
#define Nn 256
#define DDd 64

// Scratch (device globals — no allocations allowed)
__device__ float g_U[3u*3*Bb*Nn*Dd];       // [x][d][b][t][c] pooled GEMM inputs
__device__ float g_G[3u*3*Bb*Nn*Dd];       // [x][d][b][t][c] GEMM outputs
__device__ float g_pool[3u*Bb*Hh*Nn*DDd];  // [x][b][h][t][dd]
__device__ float g_attn[(unsigned)Bb*Hh*Nn*DDd];   // [b][h][t][dd]
__device__ float g_oproj[(unsigned)Bb*Nn*Dd];      // [b][t][c]
__device__ float g_final[(unsigned)Bb*Nn*Dd];      // [b][t][c]

// ---------------------------------------------------------------------------
// Pool kernel: for each input x (q,k,v), conv tap d, batch b, pooled pos t:
// U[x][d][b][t][c] = sum_{j in J_t, j+d-2 >= 0} x[b, j+d-2, c]
// J_t = [max(0,8t-7), 8t]. Implemented via 10-tap window regs (zero for idx<0).
// ---------------------------------------------------------------------------
__global__ void __launch_bounds__(256) pool_kernel(const float* __restrict__ q,
                                                   const float* __restrict__ k,
                                                   const float* __restrict__ v) {
    const int t = blockIdx.x;   // 0..255
    const int b = blockIdx.y;   // 0..3
    const int x = blockIdx.z;   // 0..2
    const float* src = (x == 0) ? q : ((x == 1) ? k : v);
    const int base = 8 * t - 9;
    const int jlo = (8 * t - 7 > 0) ? (8 * t - 7) : 0;
    const size_t dstride = (size_t)Bb * Nn * Dd;
    float* Ux = g_U + (size_t)x * 3 * dstride;

    for (int c = threadIdx.x; c < Dd; c += 256) {
        float vv[10];
        #pragma unroll
        for (int kk = 0; kk < 10; kk++) {
            int i = base + kk;
            vv[kk] = (i >= 0) ? src[((size_t)b * Ss + i) * Dd + c] : 0.0f;
        }
        float s0 = 0.f, s1 = 0.f, s2 = 0.f;
        for (int j = jlo; j <= 8 * t; j++) {
            int jj = j - base;          // in [2..9]
            s0 += vv[jj - 2];
            s1 += vv[jj - 1];
            s2 += vv[jj - 0];
        }
        size_t row = (((size_t)b) * Nn + t) * Dd + c;
        Ux[row] = s0;
        Ux[row + dstride] = s1;
        Ux[row + 2 * dstride] = s2;
    }
}

// ---------------------------------------------------------------------------
// SGEMM: C[M,N] = A[M,K] @ B[K,N] (+ bias[N]).  M%128==0, N%128==0, K%8==0.
// 128x128 block tile, 8x8 per-thread microtile, 256 threads.
// ---------------------------------------------------------------------------
__global__ void __launch_bounds__(256) sgemm128(const float* __restrict__ A,
                                                const float* __restrict__ Bm,
                                                const float* __restrict__ bias,
                                                float* __restrict__ C,
                                                int M, int N, int K) {
    __shared__ float As[8][128];
    __shared__ float Bs[8][128];
    const int tid = threadIdx.x;
    const int bm = blockIdx.y, bn = blockIdx.x;
    const int arow = tid >> 1, acol = (tid & 1) << 2;
    const int brow = tid >> 5, bcol = (tid & 31) << 2;
    const int ty = tid >> 4, tx = tid & 15;

    float acc[8][8];
    #pragma unroll
    for (int i = 0; i < 8; i++)
        #pragma unroll
        for (int j = 0; j < 8; j++) acc[i][j] = 0.f;

    const float* Ap = A + (size_t)(bm * 128 + arow) * K + acol;
    const float* Bp = Bm + (size_t)brow * N + bn * 128 + bcol;

    for (int kt = 0; kt < K; kt += 8) {
        float4 av = *(const float4*)(Ap + kt);
        float4 bv = *(const float4*)(Bp + (size_t)kt * N);
        As[acol + 0][arow] = av.x;
        As[acol + 1][arow] = av.y;
        As[acol + 2][arow] = av.z;
        As[acol + 3][arow] = av.w;
        *(float4*)&Bs[brow][bcol] = bv;
        __syncthreads();
        #pragma unroll
        for (int kk = 0; kk < 8; kk++) {
            float ra[8], rb[8];
            *(float4*)&ra[0] = *(const float4*)&As[kk][ty * 8];
            *(float4*)&ra[4] = *(const float4*)&As[kk][ty * 8 + 4];
            *(float4*)&rb[0] = *(const float4*)&Bs[kk][tx * 8];
            *(float4*)&rb[4] = *(const float4*)&Bs[kk][tx * 8 + 4];
            #pragma unroll
            for (int i = 0; i < 8; i++)
                #pragma unroll
                for (int j = 0; j < 8; j++) acc[i][j] += ra[i] * rb[j];
        }
        __syncthreads();
    }

    #pragma unroll
    for (int i = 0; i < 8; i++) {
        int row = bm * 128 + ty * 8 + i;
        float* Cp = C + (size_t)row * N + bn * 128 + tx * 8;
        float4 o0 = make_float4(acc[i][0], acc[i][1], acc[i][2], acc[i][3]);
        float4 o1 = make_float4(acc[i][4], acc[i][5], acc[i][6], acc[i][7]);
        if (bias) {
            const float* bp = bias + bn * 128 + tx * 8;
            o0.x += bp[0]; o0.y += bp[1]; o0.z += bp[2]; o0.w += bp[3];
            o1.x += bp[4]; o1.y += bp[5]; o1.z += bp[6]; o1.w += bp[7];
        }
        *(float4*)Cp = o0;
        *(float4*)(Cp + 4) = o1;
    }
}

// ---------------------------------------------------------------------------
// Combine: fold conv weights + both biases + norm scale + /8 into pooled q/k/v.
// pooled[x][b][h][t][dd] =
//   (1/8) * ( cJ*bconv[c] + scale * sum_d w[d,c]*(G_d[t,c] + cnt[t,d]*bdense[c]) )
// ---------------------------------------------------------------------------
__global__ void __launch_bounds__(256) combine_kernel(
        const float* __restrict__ wcq, const float* __restrict__ bcq, const float* __restrict__ bq,
        const float* __restrict__ wck, const float* __restrict__ bck, const float* __restrict__ bk,
        const float* __restrict__ wcv, const float* __restrict__ bcv, const float* __restrict__ bv) {
    const int t = blockIdx.x, b = blockIdx.y, x = blockIdx.z;
    const float* wc = (x == 0) ? wcq : ((x == 1) ? wck : wcv);
    const float* bc = (x == 0) ? bcq : ((x == 1) ? bck : bcv);
    const float* bd = (x == 0) ? bq  : ((x == 1) ? bk  : bv);
    const float scale = (x == 2) ? 1.0f : 0.35355339059327379f;  // 64^-0.25

    float cJ, c0, c1, c2;
    if (t == 0)      { cJ = 1.f; c0 = 0.f; c1 = 0.f; c2 = 1.f; }
    else if (t == 1) { cJ = 8.f; c0 = 7.f; c1 = 8.f; c2 = 8.f; }
    else             { cJ = 8.f; c0 = 8.f; c1 = 8.f; c2 = 8.f; }

    const size_t ds = (size_t)Bb * Nn * Dd;
    const size_t base0 = ((((size_t)x * 3 + 0) * Bb + b) * Nn + t) * Dd;

    for (int c = threadIdx.x; c < Dd; c += 256) {
        float G0 = g_G[base0 + c];
        float G1 = g_G[base0 + ds + c];
        float G2 = g_G[base0 + 2 * ds + c];
        float bdc = bd[c];
        float val = cJ * bc[c] + scale * (wc[c]          * (G0 + c0 * bdc) +
                                          wc[Dd + c]     * (G1 + c1 * bdc) +
                                          wc[2 * Dd + c] * (G2 + c2 * bdc));
        val *= 0.125f;
        int h = c >> 6, dd = c & 63;
        g_pool[((((size_t)x * Bb + b) * Hh + h) * Nn + t) * DDd + dd] = val;
    }
}

// ---------------------------------------------------------------------------
// Attention: one block per (b,h). 256 threads = one query row each.
// Causal mask applied exactly by skipping m > i (identical to -1e9 + softmax
// in fp32: masked exps underflow to 0 and never set the max).
// ---------------------------------------------------------------------------
__global__ void __launch_bounds__(256) attn_kernel() {
    const int bh = blockIdx.x;  // 0..63
    __shared__ float sK[64][DDd];
    __shared__ float sV[64][DDd];
    const float* qp = g_pool + ((size_t)0 * Bb * Hh + bh) * Nn * DDd;
    const float* kp = g_pool + ((size_t)1 * Bb * Hh + bh) * Nn * DDd;
    const float* vp = g_pool + ((size_t)2 * Bb * Hh + bh) * Nn * DDd;
    const int i = threadIdx.x;

    float qreg[DDd];
    #pragma unroll
    for (int d = 0; d < DDd; d++) qreg[d] = qp[(size_t)i * DDd + d];

    float mi = -1e30f, li = 0.f;
    float acc[DDd];
    #pragma unroll
    for (int d = 0; d < DDd; d++) acc[d] = 0.f;

    for (int kt = 0; kt < Nn; kt += 64) {
        for (int idx = threadIdx.x; idx < 64 * DDd / 4; idx += 256) {
            ((float4*)&sK[0][0])[idx] = ((const float4*)(kp + (size_t)kt * DDd))[idx];
            ((float4*)&sV[0][0])[idx] = ((const float4*)(vp + (size_t)kt * DDd))[idx];
        }
        __syncthreads();
        int mmax = i - kt; if (mmax > 63) mmax = 63;
        for (int m = 0; m <= mmax; m++) {
            float d0 = 0.f, d1 = 0.f, d2 = 0.f, d3 = 0.f;
            #pragma unroll
            for (int d = 0; d < DDd; d += 4) {
                d0 += qreg[d + 0] * sK[m][d + 0];
                d1 += qreg[d + 1] * sK[m][d + 1];
                d2 += qreg[d + 2] * sK[m][d + 2];
                d3 += qreg[d + 3] * sK[m][d + 3];
            }
            float dot = (d0 + d1) + (d2 + d3);
            if (dot > mi) {
                float f = __expf(mi - dot);
                li *= f;
                #pragma unroll
                for (int d = 0; d < DDd; d++) acc[d] *= f;
                mi = dot;
            }
            float p = __expf(dot - mi);
            li += p;
            #pragma unroll
            for (int d = 0; d < DDd; d++) acc[d] += p * sV[m][d];
        }
        __syncthreads();
    }

    float inv = 1.0f / li;
    float* outp = g_attn + ((size_t)bh * Nn + i) * DDd;
    #pragma unroll
    for (int d = 0; d < DDd; d++) outp[d] = acc[d] * inv;
}

// ---------------------------------------------------------------------------
// Per-head up-projection (Wup [64,64]) + head merge into [B,n,D]
// ---------------------------------------------------------------------------
__global__ void __launch_bounds__(256) up_kernel(const float* __restrict__ Wup,
                                                 const float* __restrict__ bup) {
    const int bt = blockIdx.x;           // 0..B*N-1
    const int b = bt >> 8, t = bt & 255;
    __shared__ float sW[DDd * DDd];
    __shared__ float sIn[Hh * DDd];
    for (int idx = threadIdx.x; idx < DDd * DDd; idx += 256) sW[idx] = Wup[idx];
    for (int idx = threadIdx.x; idx < Hh * DDd; idx += 256) {
        int h = idx >> 6, dd = idx & 63;
        sIn[idx] = g_attn[(((size_t)b * Hh + h) * Nn + t) * DDd + dd];
    }
    __syncthreads();
    for (int c = threadIdx.x; c < Dd; c += 256) {
        int h = c >> 6, ddp = c & 63;
        float s = bup[ddp];
        #pragma unroll
        for (int dd = 0; dd < DDd; dd++) s += sIn[h * DDd + dd] * sW[dd * DDd + ddp];
        g_oproj[((size_t)b * Nn + t) * Dd + c] = s;
    }
}

// ---------------------------------------------------------------------------
// Broadcast: output rows repeat every KP=8 sequence positions.
// ---------------------------------------------------------------------------
__global__ void __launch_bounds__(256) bcast_kernel(float* __restrict__ out) {
    const int total4 = Bb * Ss * Dd / 4;
    int idx = blockIdx.x * blockDim.x + threadIdx.x;
    if (idx >= total4) return;
    size_t e = (size_t)idx * 4;
    int c = (int)(e % Dd);
    size_t row = e / Dd;                 // b*S + s
    int b = (int)(row / Ss);
    int s = (int)(row % Ss);
    float4 v = *(const float4*)&g_final[(((size_t)b * Nn) + (s >> 3)) * Dd + c];
    *(float4*)&out[e] = v;
}

// ---------------------------------------------------------------------------
extern "C" void kernel_launch(void* const* d_in, const int* in_sizes, int n_in,
                              void* d_out, int out_size) {
    const float* q   = (const float*)d_in[0];
    const float* k   = (const float*)d_in[1];
    const float* v   = (const float*)d_in[2];
    const float* Wq  = (const float*)d_in[3];
    const float* bq  = (const float*)d_in[4];
    const float* Wk  = (const float*)d_in[5];
    const float* bk  = (const float*)d_in[6];
    const float* Wv  = (const float*)d_in[7];
    const float* bv  = (const float*)d_in[8];
    const float* Wup = (const float*)d_in[9];
    const float* bup = (const float*)d_in[10];
    const float* Wc  = (const float*)d_in[11];
    const float* bc  = (const float*)d_in[12];
    const float* wcq = (const float*)d_in[13];
    const float* bcq = (const float*)d_in[14];
    const float* wck = (const float*)d_in[15];
    const float* bck = (const float*)d_in[16];
    const float* wcv = (const float*)d_in[17];
    const float* bcv = (const float*)d_in[18];

    float *pU, *pG, *pOproj, *pFinal;
    cudaGetSymbolAddress((void**)&pU, g_U);
    cudaGetSymbolAddress((void**)&pG, g_G);
    cudaGetSymbolAddress((void**)&pOproj, g_oproj);
    cudaGetSymbolAddress((void**)&pFinal, g_final);

    // 1. Pooled GEMM inputs (fuses dw-conv decomposition + causal avg-pool)
    pool_kernel<<<dim3(Nn, Bb, 3), 256>>>(q, k, v);

    // 2. Projection GEMMs on pooled rows: 3 x [3072,1024]@[1024,1024]
    const size_t xoff = (size_t)3 * Bb * Nn * Dd;
    const float* Ws[3] = {Wq, Wk, Wv};
    for (int x = 0; x < 3; x++) {
        sgemm128<<<dim3(Dd / 128, (3 * Bb * Nn) / 128), 256>>>(
            pU + x * xoff, Ws[x], nullptr, pG + x * xoff, 3 * Bb * Nn, Dd, Dd);
    }

    // 3. Combine conv weights/biases/scale -> pooled q/k/v [x][b][h][t][dd]
    combine_kernel<<<dim3(Nn, Bb, 3), 256>>>(wcq, bcq, bq, wck, bck, bk, wcv, bcv, bv);

    // 4. Causal attention over pooled tokens (n=256, DD=64), per (b,h)
    attn_kernel<<<Bb * Hh, 256>>>();

    // 5. Per-head Wup + merge heads -> [B,n,D]
    up_kernel<<<Bb * Nn, 256>>>(Wup, bup);

    // 6. Final dense Wc on pooled rows only: [1024,1024]@[1024,1024] + bias
    sgemm128<<<dim3(Dd / 128, (Bb * Nn) / 128), 256>>>(
        pOproj, Wc, bc, pFinal, Bb * Nn, Dd, Dd);

    // 7. Broadcast each pooled row to its 8 sequence positions
    bcast_kernel<<<(Bb * Ss * Dd / 4 + 255) / 256, 256>>>((float*)d_out);
}

// round 3
// speedup vs baseline: 2.4199x; 2.4199x over previous
#include <cuda_runtime.h>
#include <cuda_bf16.h>
#include <stdint.h>
#include <math.h>

#define Bb 4
#define Ss 2048
#define Dd 1024
#define Hh 16
#define Nn 256
#define DDd 64

// ---------------- scratch (device globals; no allocation allowed) ----------
__device__ __nv_bfloat16 g_Uhi[9216 * 1024];      // pooled GEMM A hi [x][d][b][t] x K
__device__ __nv_bfloat16 g_Ulo[9216 * 1024];      // lo part
__device__ float g_G[9216 * 1024];                // projection GEMM outputs
__device__ __nv_bfloat16 g_Whi[4 * 1024 * 1024];  // transposed weights [N,K] hi (q,k,v,c)
__device__ __nv_bfloat16 g_Wlo[4 * 1024 * 1024];  // lo
__device__ float g_pool[3 * Bb * Hh * Nn * DDd];  // [x][b][h][t][dd]
__device__ float g_attn[Bb * Hh * Nn * DDd];      // [b][h][t][dd]
__device__ __nv_bfloat16 g_OPhi[1024 * 1024];     // up-proj output hi [b*t][c]
__device__ __nv_bfloat16 g_OPlo[1024 * 1024];
__device__ float g_final[1024 * 1024];            // final dense output [b*t][c]

// ---------------- PTX helpers ----------------------------------------------
static __device__ __forceinline__ uint32_t smem_u32(const void* p) {
    uint32_t r;
    asm("{ .reg .u64 t; cvta.to.shared.u64 t, %1; cvt.u32.u64 %0, t; }" : "=r"(r) : "l"(p));
    return r;
}
static __device__ __forceinline__ void cp16(uint32_t dst, const void* src) {
    asm volatile("cp.async.cg.shared.global [%0], [%1], 16;" :: "r"(dst), "l"(src));
}
#define CP_COMMIT() asm volatile("cp.async.commit_group;" ::: "memory")
#define CP_WAIT1()  asm volatile("cp.async.wait_group 1;" ::: "memory")

static __device__ __forceinline__ void ldsm_x4(uint32_t* r, uint32_t addr) {
    asm volatile("ldmatrix.sync.aligned.m8n8.x4.shared.b16 {%0,%1,%2,%3}, [%4];"
                 : "=r"(r[0]), "=r"(r[1]), "=r"(r[2]), "=r"(r[3]) : "r"(addr));
}
static __device__ __forceinline__ void ldsm_x2(uint32_t* r, uint32_t addr) {
    asm volatile("ldmatrix.sync.aligned.m8n8.x2.shared.b16 {%0,%1}, [%2];"
                 : "=r"(r[0]), "=r"(r[1]) : "r"(addr));
}
static __device__ __forceinline__ void mma_bf16(float* c, const uint32_t* a, const uint32_t* b) {
    asm volatile(
        "mma.sync.aligned.m16n8k16.row.col.f32.bf16.bf16.f32 "
        "{%0,%1,%2,%3}, {%4,%5,%6,%7}, {%8,%9}, {%0,%1,%2,%3};"
        : "+f"(c[0]), "+f"(c[1]), "+f"(c[2]), "+f"(c[3])
        : "r"(a[0]), "r"(a[1]), "r"(a[2]), "r"(a[3]), "r"(b[0]), "r"(b[1]));
}

// ---------------------------------------------------------------------------
// Pool kernel: pooled window sums for the 3 conv-tap-shifted variants of each
// input (q,k,v). Writes hi/lo bf16 GEMM-A rows: row = ((x*3+d)*Bb+b)*Nn + t.
// ---------------------------------------------------------------------------
__global__ void __launch_bounds__(256) pool_kernel(const float* __restrict__ q,
                                                   const float* __restrict__ k,
                                                   const float* __restrict__ v) {
    const int t = blockIdx.x, b = blockIdx.y, x = blockIdx.z;
    const float* src = (x == 0) ? q : ((x == 1) ? k : v);
    const int base = 8 * t - 9;
    const int jlo = (8 * t - 7 > 0) ? (8 * t - 7) : 0;

    for (int c = threadIdx.x; c < Dd; c += 256) {
        float vv[10];
        #pragma unroll
        for (int kk = 0; kk < 10; kk++) {
            int i = base + kk;
            vv[kk] = (i >= 0) ? src[((size_t)b * Ss + i) * Dd + c] : 0.0f;
        }
        float s[3] = {0.f, 0.f, 0.f};
        for (int j = jlo; j <= 8 * t; j++) {
            int jj = j - base;
            s[0] += vv[jj - 2];
            s[1] += vv[jj - 1];
            s[2] += vv[jj - 0];
        }
        #pragma unroll
        for (int d = 0; d < 3; d++) {
            size_t row = (((size_t)(x * 3 + d)) * Bb + b) * Nn + t;
            __nv_bfloat16 h = __float2bfloat16(s[d]);
            g_Uhi[row * Dd + c] = h;
            g_Ulo[row * Dd + c] = __float2bfloat16(s[d] - __bfloat162float(h));
        }
    }
}

// ---------------------------------------------------------------------------
// Weight prep: transpose W [K,N] -> [N,K] and split into hi/lo bf16.
// ---------------------------------------------------------------------------
__global__ void __launch_bounds__(256) wprep_kernel(const float* __restrict__ W0,
                                                    const float* __restrict__ W1,
                                                    const float* __restrict__ W2,
                                                    const float* __restrict__ W3) {
    const int z = blockIdx.z;
    const float* W = (z == 0) ? W0 : ((z == 1) ? W1 : ((z == 2) ? W2 : W3));
    __nv_bfloat16* Oh = g_Whi + (size_t)z * 1024 * 1024;
    __nv_bfloat16* Ol = g_Wlo + (size_t)z * 1024 * 1024;
    __shared__ float tile[32][33];
    const int n0 = blockIdx.x * 32, k0 = blockIdx.y * 32;
    const int tx = threadIdx.x & 31, ty = threadIdx.x >> 5;
    #pragma unroll
    for (int j = 0; j < 4; j++)
        tile[ty + j * 8][tx] = W[(size_t)(k0 + ty + j * 8) * 1024 + n0 + tx];
    __syncthreads();
    #pragma unroll
    for (int j = 0; j < 4; j++) {
        float val = tile[tx][ty + j * 8];
        __nv_bfloat16 h = __float2bfloat16(val);
        size_t o = (size_t)(n0 + ty + j * 8) * 1024 + k0 + tx;
        Oh[o] = h;
        Ol[o] = __float2bfloat16(val - __bfloat162float(h));
    }
}

// ---------------------------------------------------------------------------
// HMMA split-precision GEMM: C[M,1024] = (Ahi+Alo) @ (Bhi+Blo)^T, B as [N,K].
// CTA tile 128x128, K-step 32, double-buffered cp.async, 8 warps (2x4),
// warp tile 32x64, 3 mma terms (hi*hi + hi*lo + lo*hi), fp32 accumulators.
// SMEM rows padded to 80B -> conflict-free ldmatrix.
// ---------------------------------------------------------------------------
#define ABUF 10240            // 128 rows * 80B
#define BUFSZ (4 * ABUF)      // Ahi, Alo, Bhi, Blo
#define GEMM_SMEM (2 * BUFSZ) // double buffered (81920 B)

__global__ void __launch_bounds__(256, 1) gemm_tc(
        const __nv_bfloat16* __restrict__ Ahi, const __nv_bfloat16* __restrict__ Alo,
        const __nv_bfloat16* __restrict__ B0h, const __nv_bfloat16* __restrict__ B0l,
        const __nv_bfloat16* __restrict__ B1h, const __nv_bfloat16* __restrict__ B1l,
        const __nv_bfloat16* __restrict__ B2h, const __nv_bfloat16* __restrict__ B2l,
        float* __restrict__ C, const float* __restrict__ bias, int mblocks_per_x) {
    extern __shared__ char dsm[];
    const uint32_t sbase = smem_u32(dsm);
    const int tid = threadIdx.x;
    const int wid = tid >> 5, lane = tid & 31;
    const int bn = blockIdx.x, bm = blockIdx.y;
    const int x = bm / mblocks_per_x;
    const __nv_bfloat16* Bh = (x == 0) ? B0h : ((x == 1) ? B1h : B2h);
    const __nv_bfloat16* Bl = (x == 0) ? B0l : ((x == 1) ? B1l : B2l);

    const int warpM = wid >> 1;          // 0..3 -> 32-row slice
    const int warpN = wid & 1;           // 0..1 -> 64-col slice
    const int l16 = lane & 15;
    const uint32_t aOff = (uint32_t)((warpM * 32 + l16) * 80 + (lane >> 4) * 16);
    const uint32_t bOff = (uint32_t)(2 * ABUF + (warpN * 64 + (lane & 7)) * 80 + ((lane >> 3) & 1) * 16);

    float acc[2][8][4];
    #pragma unroll
    for (int mi = 0; mi < 2; mi++)
        #pragma unroll
        for (int ni = 0; ni < 8; ni++)
            #pragma unroll
            for (int j = 0; j < 4; j++) acc[mi][ni][j] = 0.f;

    auto load_chunk = [&](int ch, int buf) {
        const uint32_t bb = sbase + buf * BUFSZ;
        const int kof = ch * 32;
        #pragma unroll
        for (int it = 0; it < 2; it++) {
            int idx = tid + it * 256;
            int r = idx >> 2, qq = idx & 3;
            uint32_t dst = bb + r * 80 + qq * 16;
            size_t g = (size_t)(bm * 128 + r) * 1024 + kof + qq * 8;
            cp16(dst, Ahi + g);
            cp16(dst + ABUF, Alo + g);
        }
        #pragma unroll
        for (int it = 0; it < 2; it++) {
            int idx = tid + it * 256;
            int r = idx >> 2, qq = idx & 3;
            uint32_t dst = bb + 2 * ABUF + r * 80 + qq * 16;
            size_t g = (size_t)(bn * 128 + r) * 1024 + kof + qq * 8;
            cp16(dst, Bh + g);
            cp16(dst + ABUF, Bl + g);
        }
        CP_COMMIT();
    };

    load_chunk(0, 0);
    for (int i = 0; i < 32; i++) {
        if (i + 1 < 32) load_chunk(i + 1, (i + 1) & 1);
        else CP_COMMIT();
        CP_WAIT1();
        __syncthreads();
        const uint32_t bb = sbase + (i & 1) * BUFSZ;
        #pragma unroll
        for (int kk = 0; kk < 2; kk++) {
            uint32_t ah[2][4], al[2][4];
            #pragma unroll
            for (int mi = 0; mi < 2; mi++) {
                uint32_t a = bb + aOff + mi * 1280 + kk * 32;
                ldsm_x4(ah[mi], a);
                ldsm_x4(al[mi], a + ABUF);
            }
            #pragma unroll
            for (int ni = 0; ni < 8; ni++) {
                uint32_t bhf[2], blf[2];
                uint32_t ba = bb + bOff + ni * 640 + kk * 32;
                ldsm_x2(bhf, ba);
                ldsm_x2(blf, ba + ABUF);
                #pragma unroll
                for (int mi = 0; mi < 2; mi++) {
                    mma_bf16(acc[mi][ni], ah[mi], bhf);
                    mma_bf16(acc[mi][ni], ah[mi], blf);
                    mma_bf16(acc[mi][ni], al[mi], bhf);
                }
            }
        }
        __syncthreads();
    }

    // Epilogue
    const int row0 = bm * 128 + warpM * 32 + (lane >> 2);
    const int col0 = bn * 128 + warpN * 64 + (lane & 3) * 2;
    #pragma unroll
    for (int mi = 0; mi < 2; mi++) {
        #pragma unroll
        for (int ni = 0; ni < 8; ni++) {
            int r = row0 + mi * 16;
            int c = col0 + ni * 8;
            float b0 = 0.f, b1 = 0.f;
            if (bias) { b0 = bias[c]; b1 = bias[c + 1]; }
            float2 v0 = make_float2(acc[mi][ni][0] + b0, acc[mi][ni][1] + b1);
            float2 v1 = make_float2(acc[mi][ni][2] + b0, acc[mi][ni][3] + b1);
            *(float2*)&C[(size_t)r * 1024 + c] = v0;
            *(float2*)&C[(size_t)(r + 8) * 1024 + c] = v1;
        }
    }
}

// ---------------------------------------------------------------------------
// Combine: fold conv weights + biases + norm scale + /8 into pooled q/k/v.
// ---------------------------------------------------------------------------
__global__ void __launch_bounds__(256) combine_kernel(
        const float* __restrict__ wcq, const float* __restrict__ bcq, const float* __restrict__ bq,
        const float* __restrict__ wck, const float* __restrict__ bck, const float* __restrict__ bk,
        const float* __restrict__ wcv, const float* __restrict__ bcv, const float* __restrict__ bv) {
    const int t = blockIdx.x, b = blockIdx.y, x = blockIdx.z;
    const float* wc = (x == 0) ? wcq : ((x == 1) ? wck : wcv);
    const float* bc = (x == 0) ? bcq : ((x == 1) ? bck : bcv);
    const float* bd = (x == 0) ? bq  : ((x == 1) ? bk  : bv);
    const float scale = (x == 2) ? 1.0f : 0.35355339059327379f;  // 64^-0.25

    float cJ, c0, c1, c2;
    if (t == 0)      { cJ = 1.f; c0 = 0.f; c1 = 0.f; c2 = 1.f; }
    else if (t == 1) { cJ = 8.f; c0 = 7.f; c1 = 8.f; c2 = 8.f; }
    else             { cJ = 8.f; c0 = 8.f; c1 = 8.f; c2 = 8.f; }

    const size_t ds = (size_t)Bb * Nn * Dd;
    const size_t base0 = ((((size_t)x * 3 + 0) * Bb + b) * Nn + t) * Dd;

    for (int c = threadIdx.x; c < Dd; c += 256) {
        float G0 = g_G[base0 + c];
        float G1 = g_G[base0 + ds + c];
        float G2 = g_G[base0 + 2 * ds + c];
        float bdc = bd[c];
        float val = cJ * bc[c] + scale * (wc[c]          * (G0 + c0 * bdc) +
                                          wc[Dd + c]     * (G1 + c1 * bdc) +
                                          wc[2 * Dd + c] * (G2 + c2 * bdc));
        val *= 0.125f;
        int h = c >> 6, dd = c & 63;
        g_pool[((((size_t)x * Bb + b) * Hh + h) * Nn + t) * DDd + dd] = val;
    }
}

// ---------------------------------------------------------------------------
// Attention per (b,h): thread i = query row i, online softmax, causal skip.
// ---------------------------------------------------------------------------
__global__ void __launch_bounds__(256) attn_kernel() {
    const int bh = blockIdx.x;
    __shared__ float sK[64][DDd];
    __shared__ float sV[64][DDd];
    const float* qp = g_pool + ((size_t)0 * Bb * Hh + bh) * Nn * DDd;
    const float* kp = g_pool + ((size_t)1 * Bb * Hh + bh) * Nn * DDd;
    const float* vp = g_pool + ((size_t)2 * Bb * Hh + bh) * Nn * DDd;
    const int i = threadIdx.x;

    float qreg[DDd];
    #pragma unroll
    for (int d = 0; d < DDd; d++) qreg[d] = qp[(size_t)i * DDd + d];

    float mi = -1e30f, li = 0.f;
    float acc[DDd];
    #pragma unroll
    for (int d = 0; d < DDd; d++) acc[d] = 0.f;

    for (int kt = 0; kt < Nn; kt += 64) {
        for (int idx = threadIdx.x; idx < 64 * DDd / 4; idx += 256) {
            ((float4*)&sK[0][0])[idx] = ((const float4*)(kp + (size_t)kt * DDd))[idx];
            ((float4*)&sV[0][0])[idx] = ((const float4*)(vp + (size_t)kt * DDd))[idx];
        }
        __syncthreads();
        int mmax = i - kt; if (mmax > 63) mmax = 63;
        for (int m = 0; m <= mmax; m++) {
            float d0 = 0.f, d1 = 0.f, d2 = 0.f, d3 = 0.f;
            #pragma unroll
            for (int d = 0; d < DDd; d += 4) {
                d0 += qreg[d + 0] * sK[m][d + 0];
                d1 += qreg[d + 1] * sK[m][d + 1];
                d2 += qreg[d + 2] * sK[m][d + 2];
                d3 += qreg[d + 3] * sK[m][d + 3];
            }
            float dot = (d0 + d1) + (d2 + d3);
            if (dot > mi) {
                float f = __expf(mi - dot);
                li *= f;
                #pragma unroll
                for (int d = 0; d < DDd; d++) acc[d] *= f;
                mi = dot;
            }
            float p = __expf(dot - mi);
            li += p;
            #pragma unroll
            for (int d = 0; d < DDd; d++) acc[d] += p * sV[m][d];
        }
        __syncthreads();
    }

    float inv = 1.0f / li;
    float* outp = g_attn + ((size_t)bh * Nn + i) * DDd;
    #pragma unroll
    for (int d = 0; d < DDd; d++) outp[d] = acc[d] * inv;
}

// ---------------------------------------------------------------------------
// Up-projection (Wup [64,64] per head) + merge -> hi/lo bf16 rows for Wc GEMM
// ---------------------------------------------------------------------------
__global__ void __launch_bounds__(256) up_kernel(const float* __restrict__ Wup,
                                                 const float* __restrict__ bup) {
    const int bt = blockIdx.x;
    const int b = bt >> 8, t = bt & 255;
    __shared__ float sW[DDd * DDd];
    __shared__ float sIn[Hh * DDd];
    for (int idx = threadIdx.x; idx < DDd * DDd; idx += 256) sW[idx] = Wup[idx];
    for (int idx = threadIdx.x; idx < Hh * DDd; idx += 256) {
        int h = idx >> 6, dd = idx & 63;
        sIn[idx] = g_attn[(((size_t)b * Hh + h) * Nn + t) * DDd + dd];
    }
    __syncthreads();
    for (int c = threadIdx.x; c < Dd; c += 256) {
        int h = c >> 6, ddp = c & 63;
        float s = bup[ddp];
        #pragma unroll
        for (int dd = 0; dd < DDd; dd++) s += sIn[h * DDd + dd] * sW[dd * DDd + ddp];
        size_t o = ((size_t)b * Nn + t) * Dd + c;
        __nv_bfloat16 hbf = __float2bfloat16(s);
        g_OPhi[o] = hbf;
        g_OPlo[o] = __float2bfloat16(s - __bfloat162float(hbf));
    }
}

// ---------------------------------------------------------------------------
// Broadcast: output rows repeat every KP=8 sequence positions.
// ---------------------------------------------------------------------------
__global__ void __launch_bounds__(256) bcast_kernel(float* __restrict__ out) {
    const int total4 = Bb * Ss * Dd / 4;
    int idx = blockIdx.x * blockDim.x + threadIdx.x;
    if (idx >= total4) return;
    size_t e = (size_t)idx * 4;
    int c = (int)(e % Dd);
    size_t row = e / Dd;
    int b = (int)(row / Ss);
    int s = (int)(row % Ss);
    float4 v = *(const float4*)&g_final[(((size_t)b * Nn) + (s >> 3)) * Dd + c];
    *(float4*)&out[e] = v;
}

// ---------------------------------------------------------------------------
extern "C" void kernel_launch(void* const* d_in, const int* in_sizes, int n_in,
                              void* d_out, int out_size) {
    const float* q   = (const float*)d_in[0];
    const float* k   = (const float*)d_in[1];
    const float* v   = (const float*)d_in[2];
    const float* Wq  = (const float*)d_in[3];
    const float* bq  = (const float*)d_in[4];
    const float* Wk  = (const float*)d_in[5];
    const float* bk  = (const float*)d_in[6];
    const float* Wv  = (const float*)d_in[7];
    const float* bv  = (const float*)d_in[8];
    const float* Wup = (const float*)d_in[9];
    const float* bup = (const float*)d_in[10];
    const float* Wc  = (const float*)d_in[11];
    const float* bc  = (const float*)d_in[12];
    const float* wcq = (const float*)d_in[13];
    const float* bcq = (const float*)d_in[14];
    const float* wck = (const float*)d_in[15];
    const float* bck = (const float*)d_in[16];
    const float* wcv = (const float*)d_in[17];
    const float* bcv = (const float*)d_in[18];

    __nv_bfloat16 *pUhi, *pUlo, *pWhi, *pWlo, *pOPhi, *pOPlo;
    float *pG, *pFinal;
    cudaGetSymbolAddress((void**)&pUhi, g_Uhi);
    cudaGetSymbolAddress((void**)&pUlo, g_Ulo);
    cudaGetSymbolAddress((void**)&pWhi, g_Whi);
    cudaGetSymbolAddress((void**)&pWlo, g_Wlo);
    cudaGetSymbolAddress((void**)&pOPhi, g_OPhi);
    cudaGetSymbolAddress((void**)&pOPlo, g_OPlo);
    cudaGetSymbolAddress((void**)&pG, g_G);
    cudaGetSymbolAddress((void**)&pFinal, g_final);

    cudaFuncSetAttribute(gemm_tc, cudaFuncAttributeMaxDynamicSharedMemorySize, GEMM_SMEM);

    // 1. Weight transpose + hi/lo split (Wq,Wk,Wv,Wc)
    wprep_kernel<<<dim3(32, 32, 4), 256>>>(Wq, Wk, Wv, Wc);

    // 2. Pooled GEMM inputs (dw-conv decomposition + causal pool), hi/lo bf16
    pool_kernel<<<dim3(Nn, Bb, 3), 256>>>(q, k, v);

    // 3. Fused projection GEMMs: [9216,1024] @ per-x [1024,1024]^T
    const size_t wstep = (size_t)1024 * 1024;
    gemm_tc<<<dim3(8, 72), 256, GEMM_SMEM>>>(
        pUhi, pUlo,
        pWhi + 0 * wstep, pWlo + 0 * wstep,
        pWhi + 1 * wstep, pWlo + 1 * wstep,
        pWhi + 2 * wstep, pWlo + 2 * wstep,
        pG, nullptr, 24);

    // 4. Combine conv weights/biases/scale -> pooled q/k/v
    combine_kernel<<<dim3(Nn, Bb, 3), 256>>>(wcq, bcq, bq, wck, bck, bk, wcv, bcv, bv);

    // 5. Causal attention over pooled tokens
    attn_kernel<<<Bb * Hh, 256>>>();

    // 6. Per-head Wup + merge heads -> hi/lo bf16
    up_kernel<<<Bb * Nn, 256>>>(Wup, bup);

    // 7. Final dense Wc (+bias) on pooled rows: [1024,1024] @ [1024,1024]^T
    gemm_tc<<<dim3(8, 8), 256, GEMM_SMEM>>>(
        pOPhi, pOPlo,
        pWhi + 3 * wstep, pWlo + 3 * wstep,
        pWhi + 3 * wstep, pWlo + 3 * wstep,
        pWhi + 3 * wstep, pWlo + 3 * wstep,
        pFinal, bc, 8);

    // 8. Broadcast each pooled row to its 8 sequence positions
    bcast_kernel<<<(Bb * Ss * Dd / 4 + 255) / 256, 256>>>((float*)d_out);
}

// round 4
// speedup vs baseline: 2.6335x; 1.0883x over previous
#include <cuda_runtime.h>
#include <cuda_bf16.h>
#include <stdint.h>
#include <math.h>

#define Bb 4
#define Ss 2048
#define Dd 1024
#define Hh 16
#define Nn 256
#define DDd 64

// ---------------- scratch (device globals; no allocation allowed) ----------
__device__ __nv_bfloat16 g_Uhi[9216 * 1024];      // pooled GEMM A hi [x][d][b][t] x K
__device__ __nv_bfloat16 g_Ulo[9216 * 1024];      // lo part
__device__ float g_G[9216 * 1024];                // projection GEMM outputs
__device__ __nv_bfloat16 g_Whi[4 * 1024 * 1024];  // transposed weights [N,K] hi (q,k,v,c)
__device__ __nv_bfloat16 g_Wlo[4 * 1024 * 1024];  // lo
__device__ float g_pool[3 * Bb * Hh * Nn * DDd];  // [x][b][h][t][dd]
__device__ float g_attn[Bb * Hh * Nn * DDd];      // [b][h][t][dd]
__device__ __nv_bfloat16 g_OPhi[1024 * 1024];     // up-proj output hi [b*t][c]
__device__ __nv_bfloat16 g_OPlo[1024 * 1024];
__device__ float g_final[1024 * 1024];            // final dense output [b*t][c]

// ---------------- PTX helpers ----------------------------------------------
static __device__ __forceinline__ uint32_t smem_u32(const void* p) {
    uint32_t r;
    asm("{ .reg .u64 t; cvta.to.shared.u64 t, %1; cvt.u32.u64 %0, t; }" : "=r"(r) : "l"(p));
    return r;
}
static __device__ __forceinline__ void cp16(uint32_t dst, const void* src) {
    asm volatile("cp.async.cg.shared.global [%0], [%1], 16;" :: "r"(dst), "l"(src));
}
#define CP_COMMIT() asm volatile("cp.async.commit_group;" ::: "memory")
#define CP_WAIT2()  asm volatile("cp.async.wait_group 2;" ::: "memory")

static __device__ __forceinline__ void ldsm_x4(uint32_t* r, uint32_t addr) {
    asm volatile("ldmatrix.sync.aligned.m8n8.x4.shared.b16 {%0,%1,%2,%3}, [%4];"
                 : "=r"(r[0]), "=r"(r[1]), "=r"(r[2]), "=r"(r[3]) : "r"(addr));
}
static __device__ __forceinline__ void mma_bf16(float* c, const uint32_t* a, const uint32_t* b) {
    asm volatile(
        "mma.sync.aligned.m16n8k16.row.col.f32.bf16.bf16.f32 "
        "{%0,%1,%2,%3}, {%4,%5,%6,%7}, {%8,%9}, {%0,%1,%2,%3};"
        : "+f"(c[0]), "+f"(c[1]), "+f"(c[2]), "+f"(c[3])
        : "r"(a[0]), "r"(a[1]), "r"(a[2]), "r"(a[3]), "r"(b[0]), "r"(b[1]));
}

// ---------------------------------------------------------------------------
// Pool kernel: pooled window sums for the 3 conv-tap-shifted variants of each
// input (q,k,v). Writes hi/lo bf16 GEMM-A rows: row = ((x*3+d)*Bb+b)*Nn + t.
// ---------------------------------------------------------------------------
__global__ void __launch_bounds__(256) pool_kernel(const float* __restrict__ q,
                                                   const float* __restrict__ k,
                                                   const float* __restrict__ v) {
    const int t = blockIdx.x, b = blockIdx.y, x = blockIdx.z;
    const float* src = (x == 0) ? q : ((x == 1) ? k : v);
    const int base = 8 * t - 9;
    const int jlo = (8 * t - 7 > 0) ? (8 * t - 7) : 0;

    for (int c = threadIdx.x; c < Dd; c += 256) {
        float vv[10];
        #pragma unroll
        for (int kk = 0; kk < 10; kk++) {
            int i = base + kk;
            vv[kk] = (i >= 0) ? src[((size_t)b * Ss + i) * Dd + c] : 0.0f;
        }
        float s[3] = {0.f, 0.f, 0.f};
        for (int j = jlo; j <= 8 * t; j++) {
            int jj = j - base;
            s[0] += vv[jj - 2];
            s[1] += vv[jj - 1];
            s[2] += vv[jj - 0];
        }
        #pragma unroll
        for (int d = 0; d < 3; d++) {
            size_t row = (((size_t)(x * 3 + d)) * Bb + b) * Nn + t;
            __nv_bfloat16 h = __float2bfloat16(s[d]);
            g_Uhi[row * Dd + c] = h;
            g_Ulo[row * Dd + c] = __float2bfloat16(s[d] - __bfloat162float(h));
        }
    }
}

// ---------------------------------------------------------------------------
// Weight prep: transpose W [K,N] -> [N,K] and split into hi/lo bf16.
// ---------------------------------------------------------------------------
__global__ void __launch_bounds__(256) wprep_kernel(const float* __restrict__ W0,
                                                    const float* __restrict__ W1,
                                                    const float* __restrict__ W2,
                                                    const float* __restrict__ W3) {
    const int z = blockIdx.z;
    const float* W = (z == 0) ? W0 : ((z == 1) ? W1 : ((z == 2) ? W2 : W3));
    __nv_bfloat16* Oh = g_Whi + (size_t)z * 1024 * 1024;
    __nv_bfloat16* Ol = g_Wlo + (size_t)z * 1024 * 1024;
    __shared__ float tile[32][33];
    const int n0 = blockIdx.x * 32, k0 = blockIdx.y * 32;
    const int tx = threadIdx.x & 31, ty = threadIdx.x >> 5;
    #pragma unroll
    for (int j = 0; j < 4; j++)
        tile[ty + j * 8][tx] = W[(size_t)(k0 + ty + j * 8) * 1024 + n0 + tx];
    __syncthreads();
    #pragma unroll
    for (int j = 0; j < 4; j++) {
        float val = tile[tx][ty + j * 8];
        __nv_bfloat16 h = __float2bfloat16(val);
        size_t o = (size_t)(n0 + ty + j * 8) * 1024 + k0 + tx;
        Oh[o] = h;
        Ol[o] = __float2bfloat16(val - __bfloat162float(h));
    }
}

// ---------------------------------------------------------------------------
// HMMA split-precision GEMM: C[M,1024] = (Ahi+Alo) @ (Bhi+Blo)^T, B as [N,K].
// CTA tile (64*MI) x 128, 4-stage cp.async pipeline (K-step 32), 8 warps
// (4 in M x 2 in N), warp tile (16*MI) x 64, x4 ldmatrix for A and B,
// 3 mma terms (hi*hi + hi*lo + lo*hi), fp32 accumulators.
// SMEM rows padded to 80B -> conflict-free ldmatrix. One barrier per chunk.
// ---------------------------------------------------------------------------
#define BROWS 128
#define NSTAGE 4

template <int MI>
__global__ void __launch_bounds__(256, 1) gemm_tc(
        const __nv_bfloat16* __restrict__ Ahi, const __nv_bfloat16* __restrict__ Alo,
        const __nv_bfloat16* __restrict__ B0h, const __nv_bfloat16* __restrict__ B0l,
        const __nv_bfloat16* __restrict__ B1h, const __nv_bfloat16* __restrict__ B1l,
        const __nv_bfloat16* __restrict__ B2h, const __nv_bfloat16* __restrict__ B2l,
        float* __restrict__ C, const float* __restrict__ bias, int mblocks_per_x) {
    constexpr int CTAM = 64 * MI;
    constexpr int ASZ = CTAM * 80;          // one A part (hi or lo) per stage
    constexpr int BSZ = BROWS * 80;         // one B part per stage
    constexpr int STAGE = 2 * ASZ + 2 * BSZ;

    extern __shared__ char dsm[];
    const uint32_t sbase = smem_u32(dsm);
    const int tid = threadIdx.x;
    const int wid = tid >> 5, lane = tid & 31;
    const int bn = blockIdx.x, bm = blockIdx.y;
    const int x = bm / mblocks_per_x;
    const __nv_bfloat16* Bh = (x == 0) ? B0h : ((x == 1) ? B1h : B2h);
    const __nv_bfloat16* Bl = (x == 0) ? B0l : ((x == 1) ? B1l : B2l);

    const int warpM = wid >> 1;          // 0..3
    const int warpN = wid & 1;           // 0..1
    // A ldmatrix x4: lanes 0-15 rows, lane>>4 selects 16B k-half
    const uint32_t aOff = (uint32_t)((warpM * 16 * MI + (lane & 15)) * 80 + (lane >> 4) * 16);
    // B ldmatrix x4 over a 16-row n-pair: lanes 0-7 rows0-7/k0, 8-15 rows0-7/k16B,
    // 16-23 rows8-15/k0, 24-31 rows8-15/k16B
    const uint32_t bOff = (uint32_t)(2 * ASZ +
        (warpN * 64 + ((lane >> 4) & 1) * 8 + (lane & 7)) * 80 + ((lane >> 3) & 1) * 16);

    float acc[MI][8][4];
    #pragma unroll
    for (int mi = 0; mi < MI; mi++)
        #pragma unroll
        for (int ni = 0; ni < 8; ni++)
            #pragma unroll
            for (int j = 0; j < 4; j++) acc[mi][ni][j] = 0.f;

    auto load_chunk = [&](int ch, int st) {
        const uint32_t bb = sbase + st * STAGE;
        const int kof = ch * 32;
        #pragma unroll
        for (int it = 0; it < MI; it++) {   // A: CTAM rows * 4 cp16 / 256 thr
            int idx = tid + it * 256;
            int r = idx >> 2, qq = idx & 3;
            uint32_t dst = bb + r * 80 + qq * 16;
            size_t g = (size_t)(bm * CTAM + r) * 1024 + kof + qq * 8;
            cp16(dst, Ahi + g);
            cp16(dst + ASZ, Alo + g);
        }
        #pragma unroll
        for (int it = 0; it < 2; it++) {    // B: 128 rows * 4 cp16 / 256 thr
            int idx = tid + it * 256;
            int r = idx >> 2, qq = idx & 3;
            uint32_t dst = bb + 2 * ASZ + r * 80 + qq * 16;
            size_t g = (size_t)(bn * BROWS + r) * 1024 + kof + qq * 8;
            cp16(dst, Bh + g);
            cp16(dst + BSZ, Bl + g);
        }
        CP_COMMIT();
    };

    // Prologue: fill 3 of 4 stages
    load_chunk(0, 0);
    load_chunk(1, 1);
    load_chunk(2, 2);

    for (int i = 0; i < 32; i++) {
        CP_WAIT2();              // chunk i resident (<=2 groups still in flight)
        __syncthreads();         // also protects buf (i-1)%4 from overwrite below
        const uint32_t bb = sbase + (i & 3) * STAGE;
        #pragma unroll
        for (int kk = 0; kk < 2; kk++) {
            uint32_t ah[MI][4], al[MI][4];
            #pragma unroll
            for (int mi = 0; mi < MI; mi++) {
                uint32_t a = bb + aOff + mi * 16 * 80 + kk * 32;
                ldsm_x4(ah[mi], a);
                ldsm_x4(al[mi], a + ASZ);
            }
            #pragma unroll
            for (int p = 0; p < 4; p++) {   // 4 n-pairs = 8 n8 tiles
                uint32_t bh4[4], bl4[4];
                uint32_t ba = bb + bOff + p * 16 * 80 + kk * 32;
                ldsm_x4(bh4, ba);
                ldsm_x4(bl4, ba + BSZ);
                #pragma unroll
                for (int mi = 0; mi < MI; mi++) {
                    mma_bf16(acc[mi][2 * p],     ah[mi], bh4);
                    mma_bf16(acc[mi][2 * p],     ah[mi], bl4);
                    mma_bf16(acc[mi][2 * p],     al[mi], bh4);
                    mma_bf16(acc[mi][2 * p + 1], ah[mi], bh4 + 2);
                    mma_bf16(acc[mi][2 * p + 1], ah[mi], bl4 + 2);
                    mma_bf16(acc[mi][2 * p + 1], al[mi], bh4 + 2);
                }
            }
        }
        if (i + 3 < 32) load_chunk(i + 3, (i + 3) & 3);
        else CP_COMMIT();        // keep group count uniform for wait_group
    }

    // Epilogue
    const int row0 = bm * CTAM + warpM * 16 * MI + (lane >> 2);
    const int col0 = bn * 128 + warpN * 64 + (lane & 3) * 2;
    #pragma unroll
    for (int mi = 0; mi < MI; mi++) {
        #pragma unroll
        for (int ni = 0; ni < 8; ni++) {
            int r = row0 + mi * 16;
            int c = col0 + ni * 8;
            float b0 = 0.f, b1 = 0.f;
            if (bias) { b0 = bias[c]; b1 = bias[c + 1]; }
            float2 v0 = make_float2(acc[mi][ni][0] + b0, acc[mi][ni][1] + b1);
            float2 v1 = make_float2(acc[mi][ni][2] + b0, acc[mi][ni][3] + b1);
            *(float2*)&C[(size_t)r * 1024 + c] = v0;
            *(float2*)&C[(size_t)(r + 8) * 1024 + c] = v1;
        }
    }
}

// ---------------------------------------------------------------------------
// Combine: fold conv weights + biases + norm scale + /8 into pooled q/k/v.
// ---------------------------------------------------------------------------
__global__ void __launch_bounds__(256) combine_kernel(
        const float* __restrict__ wcq, const float* __restrict__ bcq, const float* __restrict__ bq,
        const float* __restrict__ wck, const float* __restrict__ bck, const float* __restrict__ bk,
        const float* __restrict__ wcv, const float* __restrict__ bcv, const float* __restrict__ bv) {
    const int t = blockIdx.x, b = blockIdx.y, x = blockIdx.z;
    const float* wc = (x == 0) ? wcq : ((x == 1) ? wck : wcv);
    const float* bc = (x == 0) ? bcq : ((x == 1) ? bck : bcv);
    const float* bd = (x == 0) ? bq  : ((x == 1) ? bk  : bv);
    const float scale = (x == 2) ? 1.0f : 0.35355339059327379f;  // 64^-0.25

    float cJ, c0, c1, c2;
    if (t == 0)      { cJ = 1.f; c0 = 0.f; c1 = 0.f; c2 = 1.f; }
    else if (t == 1) { cJ = 8.f; c0 = 7.f; c1 = 8.f; c2 = 8.f; }
    else             { cJ = 8.f; c0 = 8.f; c1 = 8.f; c2 = 8.f; }

    const size_t ds = (size_t)Bb * Nn * Dd;
    const size_t base0 = ((((size_t)x * 3 + 0) * Bb + b) * Nn + t) * Dd;

    for (int c = threadIdx.x; c < Dd; c += 256) {
        float G0 = g_G[base0 + c];
        float G1 = g_G[base0 + ds + c];
        float G2 = g_G[base0 + 2 * ds + c];
        float bdc = bd[c];
        float val = cJ * bc[c] + scale * (wc[c]          * (G0 + c0 * bdc) +
                                          wc[Dd + c]     * (G1 + c1 * bdc) +
                                          wc[2 * Dd + c] * (G2 + c2 * bdc));
        val *= 0.125f;
        int h = c >> 6, dd = c & 63;
        g_pool[((((size_t)x * Bb + b) * Hh + h) * Nn + t) * DDd + dd] = val;
    }
}

// ---------------------------------------------------------------------------
// Attention per (b,h): thread i = query row i, online softmax, causal skip.
// ---------------------------------------------------------------------------
__global__ void __launch_bounds__(256) attn_kernel() {
    const int bh = blockIdx.x;
    __shared__ float sK[64][DDd];
    __shared__ float sV[64][DDd];
    const float* qp = g_pool + ((size_t)0 * Bb * Hh + bh) * Nn * DDd;
    const float* kp = g_pool + ((size_t)1 * Bb * Hh + bh) * Nn * DDd;
    const float* vp = g_pool + ((size_t)2 * Bb * Hh + bh) * Nn * DDd;
    const int i = threadIdx.x;

    float qreg[DDd];
    #pragma unroll
    for (int d = 0; d < DDd; d++) qreg[d] = qp[(size_t)i * DDd + d];

    float mi = -1e30f, li = 0.f;
    float acc[DDd];
    #pragma unroll
    for (int d = 0; d < DDd; d++) acc[d] = 0.f;

    for (int kt = 0; kt < Nn; kt += 64) {
        for (int idx = threadIdx.x; idx < 64 * DDd / 4; idx += 256) {
            ((float4*)&sK[0][0])[idx] = ((const float4*)(kp + (size_t)kt * DDd))[idx];
            ((float4*)&sV[0][0])[idx] = ((const float4*)(vp + (size_t)kt * DDd))[idx];
        }
        __syncthreads();
        int mmax = i - kt; if (mmax > 63) mmax = 63;
        for (int m = 0; m <= mmax; m++) {
            float d0 = 0.f, d1 = 0.f, d2 = 0.f, d3 = 0.f;
            #pragma unroll
            for (int d = 0; d < DDd; d += 4) {
                d0 += qreg[d + 0] * sK[m][d + 0];
                d1 += qreg[d + 1] * sK[m][d + 1];
                d2 += qreg[d + 2] * sK[m][d + 2];
                d3 += qreg[d + 3] * sK[m][d + 3];
            }
            float dot = (d0 + d1) + (d2 + d3);
            if (dot > mi) {
                float f = __expf(mi - dot);
                li *= f;
                #pragma unroll
                for (int d = 0; d < DDd; d++) acc[d] *= f;
                mi = dot;
            }
            float p = __expf(dot - mi);
            li += p;
            #pragma unroll
            for (int d = 0; d < DDd; d++) acc[d] += p * sV[m][d];
        }
        __syncthreads();
    }

    float inv = 1.0f / li;
    float* outp = g_attn + ((size_t)bh * Nn + i) * DDd;
    #pragma unroll
    for (int d = 0; d < DDd; d++) outp[d] = acc[d] * inv;
}

// ---------------------------------------------------------------------------
// Up-projection (Wup [64,64] per head) + merge -> hi/lo bf16 rows for Wc GEMM
// ---------------------------------------------------------------------------
__global__ void __launch_bounds__(256) up_kernel(const float* __restrict__ Wup,
                                                 const float* __restrict__ bup) {
    const int bt = blockIdx.x;
    const int b = bt >> 8, t = bt & 255;
    __shared__ float sW[DDd * DDd];
    __shared__ float sIn[Hh * DDd];
    for (int idx = threadIdx.x; idx < DDd * DDd; idx += 256) sW[idx] = Wup[idx];
    for (int idx = threadIdx.x; idx < Hh * DDd; idx += 256) {
        int h = idx >> 6, dd = idx & 63;
        sIn[idx] = g_attn[(((size_t)b * Hh + h) * Nn + t) * DDd + dd];
    }
    __syncthreads();
    for (int c = threadIdx.x; c < Dd; c += 256) {
        int h = c >> 6, ddp = c & 63;
        float s = bup[ddp];
        #pragma unroll
        for (int dd = 0; dd < DDd; dd++) s += sIn[h * DDd + dd] * sW[dd * DDd + ddp];
        size_t o = ((size_t)b * Nn + t) * Dd + c;
        __nv_bfloat16 hbf = __float2bfloat16(s);
        g_OPhi[o] = hbf;
        g_OPlo[o] = __float2bfloat16(s - __bfloat162float(hbf));
    }
}

// ---------------------------------------------------------------------------
// Broadcast: output rows repeat every KP=8 sequence positions.
// ---------------------------------------------------------------------------
__global__ void __launch_bounds__(256) bcast_kernel(float* __restrict__ out) {
    const int total4 = Bb * Ss * Dd / 4;
    int idx = blockIdx.x * blockDim.x + threadIdx.x;
    if (idx >= total4) return;
    size_t e = (size_t)idx * 4;
    int c = (int)(e % Dd);
    size_t row = e / Dd;
    int b = (int)(row / Ss);
    int s = (int)(row % Ss);
    float4 v = *(const float4*)&g_final[(((size_t)b * Nn) + (s >> 3)) * Dd + c];
    *(float4*)&out[e] = v;
}

// ---------------------------------------------------------------------------
extern "C" void kernel_launch(void* const* d_in, const int* in_sizes, int n_in,
                              void* d_out, int out_size) {
    const float* q   = (const float*)d_in[0];
    const float* k   = (const float*)d_in[1];
    const float* v   = (const float*)d_in[2];
    const float* Wq  = (const float*)d_in[3];
    const float* bq  = (const float*)d_in[4];
    const float* Wk  = (const float*)d_in[5];
    const float* bk  = (const float*)d_in[6];
    const float* Wv  = (const float*)d_in[7];
    const float* bv  = (const float*)d_in[8];
    const float* Wup = (const float*)d_in[9];
    const float* bup = (const float*)d_in[10];
    const float* Wc  = (const float*)d_in[11];
    const float* bc  = (const float*)d_in[12];
    const float* wcq = (const float*)d_in[13];
    const float* bcq = (const float*)d_in[14];
    const float* wck = (const float*)d_in[15];
    const float* bck = (const float*)d_in[16];
    const float* wcv = (const float*)d_in[17];
    const float* bcv = (const float*)d_in[18];

    __nv_bfloat16 *pUhi, *pUlo, *pWhi, *pWlo, *pOPhi, *pOPlo;
    float *pG, *pFinal;
    cudaGetSymbolAddress((void**)&pUhi, g_Uhi);
    cudaGetSymbolAddress((void**)&pUlo, g_Ulo);
    cudaGetSymbolAddress((void**)&pWhi, g_Whi);
    cudaGetSymbolAddress((void**)&pWlo, g_Wlo);
    cudaGetSymbolAddress((void**)&pOPhi, g_OPhi);
    cudaGetSymbolAddress((void**)&pOPlo, g_OPlo);
    cudaGetSymbolAddress((void**)&pG, g_G);
    cudaGetSymbolAddress((void**)&pFinal, g_final);

    // smem: MI=2: 4 * (2*128*80 + 2*128*80) = 163840 ; MI=1: 122880
    const int SM2 = 4 * (2 * 128 * 80 + 2 * 128 * 80);
    const int SM1 = 4 * (2 * 64 * 80 + 2 * 128 * 80);
    cudaFuncSetAttribute(gemm_tc<2>, cudaFuncAttributeMaxDynamicSharedMemorySize, SM2);
    cudaFuncSetAttribute(gemm_tc<1>, cudaFuncAttributeMaxDynamicSharedMemorySize, SM1);

    // 1. Weight transpose + hi/lo split (Wq,Wk,Wv,Wc)
    wprep_kernel<<<dim3(32, 32, 4), 256>>>(Wq, Wk, Wv, Wc);

    // 2. Pooled GEMM inputs (dw-conv decomposition + causal pool), hi/lo bf16
    pool_kernel<<<dim3(Nn, Bb, 3), 256>>>(q, k, v);

    // 3. Fused projection GEMMs: [9216,1024] @ per-x [1024,1024]^T
    const size_t wstep = (size_t)1024 * 1024;
    gemm_tc<2><<<dim3(8, 72), 256, SM2>>>(
        pUhi, pUlo,
        pWhi + 0 * wstep, pWlo + 0 * wstep,
        pWhi + 1 * wstep, pWlo + 1 * wstep,
        pWhi + 2 * wstep, pWlo + 2 * wstep,
        pG, nullptr, 24);

    // 4. Combine conv weights/biases/scale -> pooled q/k/v
    combine_kernel<<<dim3(Nn, Bb, 3), 256>>>(wcq, bcq, bq, wck, bck, bk, wcv, bcv, bv);

    // 5. Causal attention over pooled tokens
    attn_kernel<<<Bb * Hh, 256>>>();

    // 6. Per-head Wup + merge heads -> hi/lo bf16
    up_kernel<<<Bb * Nn, 256>>>(Wup, bup);

    // 7. Final dense Wc (+bias): 64x128 tile -> 128 CTAs = one full wave
    gemm_tc<1><<<dim3(8, 16), 256, SM1>>>(
        pOPhi, pOPlo,
        pWhi + 3 * wstep, pWlo + 3 * wstep,
        pWhi + 3 * wstep, pWlo + 3 * wstep,
        pWhi + 3 * wstep, pWlo + 3 * wstep,
        pFinal, bc, 16);

    // 8. Broadcast each pooled row to its 8 sequence positions
    bcast_kernel<<<(Bb * Ss * Dd / 4 + 255) / 256, 256>>>((float*)d_out);
}

// round 5
// speedup vs baseline: 3.4419x; 1.3070x over previous
#include <cuda_runtime.h>
#include <cuda_fp16.h>
#include <stdint.h>
#include <math.h>

#define Bb 4
#define Ss 2048
#define Dd 1024
#define Hh 16
#define Nn 256
#define DDd 64

// ---------------- scratch (device globals; no allocation allowed) ----------
__device__ __half g_Uhi[9216 * 1024];        // pooled GEMM A hi [x][d][b][t] x K
__device__ __half g_Ulo[9216 * 1024];        // lo part (exact residual)
__device__ float g_G[9216 * 1024];           // projection GEMM outputs (fp32)
__device__ __half g_Wh[4 * 1024 * 1024];     // transposed weights [N,K] fp16 (q,k,v,c)
__device__ float g_pool[3 * Bb * Hh * Nn * DDd];  // [x][b][h][t][dd]
__device__ float g_attn[Bb * Hh * Nn * DDd];      // [b][h][t][dd]
__device__ __half g_OPhi[1024 * 1024];       // up-proj output hi [b*t][c]
__device__ __half g_OPlo[1024 * 1024];

// ---------------- PTX helpers ----------------------------------------------
static __device__ __forceinline__ uint32_t smem_u32(const void* p) {
    uint32_t r;
    asm("{ .reg .u64 t; cvta.to.shared.u64 t, %1; cvt.u32.u64 %0, t; }" : "=r"(r) : "l"(p));
    return r;
}
static __device__ __forceinline__ void cp16(uint32_t dst, const void* src) {
    asm volatile("cp.async.cg.shared.global [%0], [%1], 16;" :: "r"(dst), "l"(src));
}
#define CP_COMMIT() asm volatile("cp.async.commit_group;" ::: "memory")
#define CP_WAIT1()  asm volatile("cp.async.wait_group 1;" ::: "memory")

static __device__ __forceinline__ void ldsm_x4(uint32_t* r, uint32_t addr) {
    asm volatile("ldmatrix.sync.aligned.m8n8.x4.shared.b16 {%0,%1,%2,%3}, [%4];"
                 : "=r"(r[0]), "=r"(r[1]), "=r"(r[2]), "=r"(r[3]) : "r"(addr));
}
static __device__ __forceinline__ void mma_f16(float* c, const uint32_t* a, const uint32_t* b) {
    asm volatile(
        "mma.sync.aligned.m16n8k16.row.col.f32.f16.f16.f32 "
        "{%0,%1,%2,%3}, {%4,%5,%6,%7}, {%8,%9}, {%0,%1,%2,%3};"
        : "+f"(c[0]), "+f"(c[1]), "+f"(c[2]), "+f"(c[3])
        : "r"(a[0]), "r"(a[1]), "r"(a[2]), "r"(a[3]), "r"(b[0]), "r"(b[1]));
}

// ---------------------------------------------------------------------------
// Pool kernel: pooled window sums for the 3 conv-tap-shifted variants of each
// input (q,k,v). Writes hi/lo fp16 GEMM-A rows: row = ((x*3+d)*Bb+b)*Nn + t.
// ---------------------------------------------------------------------------
__global__ void __launch_bounds__(256) pool_kernel(const float* __restrict__ q,
                                                   const float* __restrict__ k,
                                                   const float* __restrict__ v) {
    const int t = blockIdx.x, b = blockIdx.y, x = blockIdx.z;
    const float* src = (x == 0) ? q : ((x == 1) ? k : v);
    const int base = 8 * t - 9;
    const int jlo = (8 * t - 7 > 0) ? (8 * t - 7) : 0;

    for (int c = threadIdx.x; c < Dd; c += 256) {
        float vv[10];
        #pragma unroll
        for (int kk = 0; kk < 10; kk++) {
            int i = base + kk;
            vv[kk] = (i >= 0) ? src[((size_t)b * Ss + i) * Dd + c] : 0.0f;
        }
        float s[3] = {0.f, 0.f, 0.f};
        for (int j = jlo; j <= 8 * t; j++) {
            int jj = j - base;
            s[0] += vv[jj - 2];
            s[1] += vv[jj - 1];
            s[2] += vv[jj - 0];
        }
        #pragma unroll
        for (int d = 0; d < 3; d++) {
            size_t row = (((size_t)(x * 3 + d)) * Bb + b) * Nn + t;
            __half h = __float2half_rn(s[d]);
            g_Uhi[row * Dd + c] = h;
            g_Ulo[row * Dd + c] = __float2half_rn(s[d] - __half2float(h));
        }
    }
}

// ---------------------------------------------------------------------------
// Weight prep: transpose W [K,N] -> [N,K], round to fp16.
// ---------------------------------------------------------------------------
__global__ void __launch_bounds__(256) wprep_kernel(const float* __restrict__ W0,
                                                    const float* __restrict__ W1,
                                                    const float* __restrict__ W2,
                                                    const float* __restrict__ W3) {
    const int z = blockIdx.z;
    const float* W = (z == 0) ? W0 : ((z == 1) ? W1 : ((z == 2) ? W2 : W3));
    __half* Oh = g_Wh + (size_t)z * 1024 * 1024;
    __shared__ float tile[32][33];
    const int n0 = blockIdx.x * 32, k0 = blockIdx.y * 32;
    const int tx = threadIdx.x & 31, ty = threadIdx.x >> 5;
    #pragma unroll
    for (int j = 0; j < 4; j++)
        tile[ty + j * 8][tx] = W[(size_t)(k0 + ty + j * 8) * 1024 + n0 + tx];
    __syncthreads();
    #pragma unroll
    for (int j = 0; j < 4; j++) {
        float val = tile[tx][ty + j * 8];
        Oh[(size_t)(n0 + ty + j * 8) * 1024 + k0 + tx] = __float2half_rn(val);
    }
}

// ---------------------------------------------------------------------------
// HMMA split GEMM: C[M,1024] = (Ahi+Alo) @ Bh^T, A split fp16 hi/lo, B fp16.
// CTA tile (64*MI) x 128, 3-stage cp.async pipeline (K-step 32), 8 warps
// (4 in M x 2 in N), 2 mma terms (hi*B + lo*B), fp32 accumulators.
// SMEM rows padded to 80B -> conflict-free ldmatrix. 2 CTAs/SM.
// BCAST: epilogue writes each row to 8 broadcast rows of d_out [B,S,D].
// ---------------------------------------------------------------------------
#define BROWS 128

template <int MI, int BCAST>
__global__ void __launch_bounds__(256, 2) gemm_tc(
        const __half* __restrict__ Ahi, const __half* __restrict__ Alo,
        const __half* __restrict__ B0, const __half* __restrict__ B1,
        const __half* __restrict__ B2,
        float* __restrict__ C, const float* __restrict__ bias, int mblocks_per_x) {
    constexpr int CTAM = 64 * MI;
    constexpr int ASZ = CTAM * 80;          // one A part (hi or lo) per stage
    constexpr int BSZ = BROWS * 80;
    constexpr int STAGE = 2 * ASZ + BSZ;

    extern __shared__ char dsm[];
    const uint32_t sbase = smem_u32(dsm);
    const int tid = threadIdx.x;
    const int wid = tid >> 5, lane = tid & 31;
    const int bn = blockIdx.x, bm = blockIdx.y;
    const int x = bm / mblocks_per_x;
    const __half* Bh = (x == 0) ? B0 : ((x == 1) ? B1 : B2);

    const int warpM = wid >> 1;          // 0..3
    const int warpN = wid & 1;           // 0..1
    const uint32_t aOff = (uint32_t)((warpM * 16 * MI + (lane & 15)) * 80 + (lane >> 4) * 16);
    const uint32_t bOff = (uint32_t)(2 * ASZ +
        (warpN * 64 + ((lane >> 4) & 1) * 8 + (lane & 7)) * 80 + ((lane >> 3) & 1) * 16);

    float acc[MI][8][4];
    #pragma unroll
    for (int mi = 0; mi < MI; mi++)
        #pragma unroll
        for (int ni = 0; ni < 8; ni++)
            #pragma unroll
            for (int j = 0; j < 4; j++) acc[mi][ni][j] = 0.f;

    auto load_chunk = [&](int ch, int st) {
        const uint32_t bb = sbase + st * STAGE;
        const int kof = ch * 32;
        #pragma unroll
        for (int it = 0; it < MI; it++) {   // A: CTAM rows * 4 cp16 / 256 thr
            int idx = tid + it * 256;
            int r = idx >> 2, qq = idx & 3;
            uint32_t dst = bb + r * 80 + qq * 16;
            size_t g = (size_t)(bm * CTAM + r) * 1024 + kof + qq * 8;
            cp16(dst, Ahi + g);
            cp16(dst + ASZ, Alo + g);
        }
        #pragma unroll
        for (int it = 0; it < 2; it++) {    // B: 128 rows * 4 cp16 / 256 thr
            int idx = tid + it * 256;
            int r = idx >> 2, qq = idx & 3;
            uint32_t dst = bb + 2 * ASZ + r * 80 + qq * 16;
            size_t g = (size_t)(bn * BROWS + r) * 1024 + kof + qq * 8;
            cp16(dst, Bh + g);
        }
        CP_COMMIT();
    };

    // Prologue: fill 2 of 3 stages
    load_chunk(0, 0);
    load_chunk(1, 1);

    for (int i = 0; i < 32; i++) {
        CP_WAIT1();              // chunk i resident (<=1 group still in flight)
        __syncthreads();         // all warps done with chunk i-1 before overwrite
        const uint32_t bb = sbase + (i % 3) * STAGE;
        #pragma unroll
        for (int kk = 0; kk < 2; kk++) {
            uint32_t ah[MI][4], al[MI][4];
            #pragma unroll
            for (int mi = 0; mi < MI; mi++) {
                uint32_t a = bb + aOff + mi * 16 * 80 + kk * 32;
                ldsm_x4(ah[mi], a);
                ldsm_x4(al[mi], a + ASZ);
            }
            #pragma unroll
            for (int p = 0; p < 4; p++) {   // 4 n-pairs = 8 n8 tiles
                uint32_t b4[4];
                ldsm_x4(b4, bb + bOff + p * 16 * 80 + kk * 32);
                #pragma unroll
                for (int mi = 0; mi < MI; mi++) {
                    mma_f16(acc[mi][2 * p],     ah[mi], b4);
                    mma_f16(acc[mi][2 * p],     al[mi], b4);
                    mma_f16(acc[mi][2 * p + 1], ah[mi], b4 + 2);
                    mma_f16(acc[mi][2 * p + 1], al[mi], b4 + 2);
                }
            }
        }
        if (i + 2 < 32) load_chunk(i + 2, (i + 2) % 3);
        else CP_COMMIT();        // keep group count uniform for wait_group
    }

    // Epilogue
    const int row0 = bm * CTAM + warpM * 16 * MI + (lane >> 2);
    const int col0 = bn * 128 + warpN * 64 + (lane & 3) * 2;
    #pragma unroll
    for (int mi = 0; mi < MI; mi++) {
        #pragma unroll
        for (int ni = 0; ni < 8; ni++) {
            int r = row0 + mi * 16;
            int c = col0 + ni * 8;
            float b0 = 0.f, b1 = 0.f;
            if (bias) { b0 = bias[c]; b1 = bias[c + 1]; }
            float2 v0 = make_float2(acc[mi][ni][0] + b0, acc[mi][ni][1] + b1);
            float2 v1 = make_float2(acc[mi][ni][2] + b0, acc[mi][ni][3] + b1);
            if (BCAST) {
                // r in [0,1024): b = r>>8, t = r&255 -> rows b*2048 + 8t + rep
                int rb = r >> 8, rt = r & 255;
                float* o0 = C + ((size_t)rb * Ss + rt * 8) * 1024 + c;
                int r8 = r + 8;
                int rb2 = r8 >> 8, rt2 = r8 & 255;
                float* o1 = C + ((size_t)rb2 * Ss + rt2 * 8) * 1024 + c;
                #pragma unroll
                for (int rep = 0; rep < 8; rep++) {
                    *(float2*)(o0 + rep * 1024) = v0;
                    *(float2*)(o1 + rep * 1024) = v1;
                }
            } else {
                *(float2*)&C[(size_t)r * 1024 + c] = v0;
                *(float2*)&C[(size_t)(r + 8) * 1024 + c] = v1;
            }
        }
    }
}

// ---------------------------------------------------------------------------
// Combine: fold conv weights + biases + norm scale + /8 into pooled q/k/v.
// ---------------------------------------------------------------------------
__global__ void __launch_bounds__(256) combine_kernel(
        const float* __restrict__ wcq, const float* __restrict__ bcq, const float* __restrict__ bq,
        const float* __restrict__ wck, const float* __restrict__ bck, const float* __restrict__ bk,
        const float* __restrict__ wcv, const float* __restrict__ bcv, const float* __restrict__ bv) {
    const int t = blockIdx.x, b = blockIdx.y, x = blockIdx.z;
    const float* wc = (x == 0) ? wcq : ((x == 1) ? wck : wcv);
    const float* bc = (x == 0) ? bcq : ((x == 1) ? bck : bcv);
    const float* bd = (x == 0) ? bq  : ((x == 1) ? bk  : bv);
    const float scale = (x == 2) ? 1.0f : 0.35355339059327379f;  // 64^-0.25

    float cJ, c0, c1, c2;
    if (t == 0)      { cJ = 1.f; c0 = 0.f; c1 = 0.f; c2 = 1.f; }
    else if (t == 1) { cJ = 8.f; c0 = 7.f; c1 = 8.f; c2 = 8.f; }
    else             { cJ = 8.f; c0 = 8.f; c1 = 8.f; c2 = 8.f; }

    const size_t ds = (size_t)Bb * Nn * Dd;
    const size_t base0 = ((((size_t)x * 3 + 0) * Bb + b) * Nn + t) * Dd;

    for (int c = threadIdx.x; c < Dd; c += 256) {
        float G0 = g_G[base0 + c];
        float G1 = g_G[base0 + ds + c];
        float G2 = g_G[base0 + 2 * ds + c];
        float bdc = bd[c];
        float val = cJ * bc[c] + scale * (wc[c]          * (G0 + c0 * bdc) +
                                          wc[Dd + c]     * (G1 + c1 * bdc) +
                                          wc[2 * Dd + c] * (G2 + c2 * bdc));
        val *= 0.125f;
        int h = c >> 6, dd = c & 63;
        g_pool[((((size_t)x * Bb + b) * Hh + h) * Nn + t) * DDd + dd] = val;
    }
}

// ---------------------------------------------------------------------------
// Attention per (b,h): thread i = query row i, online softmax, causal skip.
// ---------------------------------------------------------------------------
__global__ void __launch_bounds__(256) attn_kernel() {
    const int bh = blockIdx.x;
    __shared__ float sK[64][DDd];
    __shared__ float sV[64][DDd];
    const float* qp = g_pool + ((size_t)0 * Bb * Hh + bh) * Nn * DDd;
    const float* kp = g_pool + ((size_t)1 * Bb * Hh + bh) * Nn * DDd;
    const float* vp = g_pool + ((size_t)2 * Bb * Hh + bh) * Nn * DDd;
    const int i = threadIdx.x;

    float qreg[DDd];
    #pragma unroll
    for (int d = 0; d < DDd; d++) qreg[d] = qp[(size_t)i * DDd + d];

    float mi = -1e30f, li = 0.f;
    float acc[DDd];
    #pragma unroll
    for (int d = 0; d < DDd; d++) acc[d] = 0.f;

    for (int kt = 0; kt < Nn; kt += 64) {
        for (int idx = threadIdx.x; idx < 64 * DDd / 4; idx += 256) {
            ((float4*)&sK[0][0])[idx] = ((const float4*)(kp + (size_t)kt * DDd))[idx];
            ((float4*)&sV[0][0])[idx] = ((const float4*)(vp + (size_t)kt * DDd))[idx];
        }
        __syncthreads();
        int mmax = i - kt; if (mmax > 63) mmax = 63;
        for (int m = 0; m <= mmax; m++) {
            float d0 = 0.f, d1 = 0.f, d2 = 0.f, d3 = 0.f;
            #pragma unroll
            for (int d = 0; d < DDd; d += 4) {
                d0 += qreg[d + 0] * sK[m][d + 0];
                d1 += qreg[d + 1] * sK[m][d + 1];
                d2 += qreg[d + 2] * sK[m][d + 2];
                d3 += qreg[d + 3] * sK[m][d + 3];
            }
            float dot = (d0 + d1) + (d2 + d3);
            if (dot > mi) {
                float f = __expf(mi - dot);
                li *= f;
                #pragma unroll
                for (int d = 0; d < DDd; d++) acc[d] *= f;
                mi = dot;
            }
            float p = __expf(dot - mi);
            li += p;
            #pragma unroll
            for (int d = 0; d < DDd; d++) acc[d] += p * sV[m][d];
        }
        __syncthreads();
    }

    float inv = 1.0f / li;
    float* outp = g_attn + ((size_t)bh * Nn + i) * DDd;
    #pragma unroll
    for (int d = 0; d < DDd; d++) outp[d] = acc[d] * inv;
}

// ---------------------------------------------------------------------------
// Up-projection (Wup [64,64] per head) + merge -> hi/lo fp16 rows for Wc GEMM
// ---------------------------------------------------------------------------
__global__ void __launch_bounds__(256) up_kernel(const float* __restrict__ Wup,
                                                 const float* __restrict__ bup) {
    const int bt = blockIdx.x;
    const int b = bt >> 8, t = bt & 255;
    __shared__ float sW[DDd * DDd];
    __shared__ float sIn[Hh * DDd];
    for (int idx = threadIdx.x; idx < DDd * DDd; idx += 256) sW[idx] = Wup[idx];
    for (int idx = threadIdx.x; idx < Hh * DDd; idx += 256) {
        int h = idx >> 6, dd = idx & 63;
        sIn[idx] = g_attn[(((size_t)b * Hh + h) * Nn + t) * DDd + dd];
    }
    __syncthreads();
    for (int c = threadIdx.x; c < Dd; c += 256) {
        int h = c >> 6, ddp = c & 63;
        float s = bup[ddp];
        #pragma unroll
        for (int dd = 0; dd < DDd; dd++) s += sIn[h * DDd + dd] * sW[dd * DDd + ddp];
        size_t o = ((size_t)b * Nn + t) * Dd + c;
        __half hbf = __float2half_rn(s);
        g_OPhi[o] = hbf;
        g_OPlo[o] = __float2half_rn(s - __half2float(hbf));
    }
}

// ---------------------------------------------------------------------------
extern "C" void kernel_launch(void* const* d_in, const int* in_sizes, int n_in,
                              void* d_out, int out_size) {
    const float* q   = (const float*)d_in[0];
    const float* k   = (const float*)d_in[1];
    const float* v   = (const float*)d_in[2];
    const float* Wq  = (const float*)d_in[3];
    const float* bq  = (const float*)d_in[4];
    const float* Wk  = (const float*)d_in[5];
    const float* bk  = (const float*)d_in[6];
    const float* Wv  = (const float*)d_in[7];
    const float* bv  = (const float*)d_in[8];
    const float* Wup = (const float*)d_in[9];
    const float* bup = (const float*)d_in[10];
    const float* Wc  = (const float*)d_in[11];
    const float* bc  = (const float*)d_in[12];
    const float* wcq = (const float*)d_in[13];
    const float* bcq = (const float*)d_in[14];
    const float* wck = (const float*)d_in[15];
    const float* bck = (const float*)d_in[16];
    const float* wcv = (const float*)d_in[17];
    const float* bcv = (const float*)d_in[18];

    __half *pUhi, *pUlo, *pWh, *pOPhi, *pOPlo;
    float *pG;
    cudaGetSymbolAddress((void**)&pUhi, g_Uhi);
    cudaGetSymbolAddress((void**)&pUlo, g_Ulo);
    cudaGetSymbolAddress((void**)&pWh, g_Wh);
    cudaGetSymbolAddress((void**)&pOPhi, g_OPhi);
    cudaGetSymbolAddress((void**)&pOPlo, g_OPlo);
    cudaGetSymbolAddress((void**)&pG, g_G);

    // smem: MI=2: 3 * (2*128*80 + 128*80) = 92160 ; MI=1: 3 * (2*64*80 + 128*80) = 61440
    const int SM2 = 3 * (2 * 128 * 80 + 128 * 80);
    const int SM1 = 3 * (2 * 64 * 80 + 128 * 80);
    cudaFuncSetAttribute((const void*)gemm_tc<2, 0>, cudaFuncAttributeMaxDynamicSharedMemorySize, SM2);
    cudaFuncSetAttribute((const void*)gemm_tc<1, 1>, cudaFuncAttributeMaxDynamicSharedMemorySize, SM1);

    // 1. Weight transpose + fp16 round (Wq,Wk,Wv,Wc)
    wprep_kernel<<<dim3(32, 32, 4), 256>>>(Wq, Wk, Wv, Wc);

    // 2. Pooled GEMM inputs (dw-conv decomposition + causal pool), hi/lo fp16
    pool_kernel<<<dim3(Nn, Bb, 3), 256>>>(q, k, v);

    // 3. Fused projection GEMMs: [9216,1024] @ per-x [1024,1024]^T
    const size_t wstep = (size_t)1024 * 1024;
    gemm_tc<2, 0><<<dim3(8, 72), 256, SM2>>>(
        pUhi, pUlo,
        pWh + 0 * wstep, pWh + 1 * wstep, pWh + 2 * wstep,
        pG, nullptr, 24);

    // 4. Combine conv weights/biases/scale -> pooled q/k/v
    combine_kernel<<<dim3(Nn, Bb, 3), 256>>>(wcq, bcq, bq, wck, bck, bk, wcv, bcv, bv);

    // 5. Causal attention over pooled tokens
    attn_kernel<<<Bb * Hh, 256>>>();

    // 6. Per-head Wup + merge heads -> hi/lo fp16
    up_kernel<<<Bb * Nn, 256>>>(Wup, bup);

    // 7. Final dense Wc (+bias), epilogue broadcasts each row to 8 seq positions
    gemm_tc<1, 1><<<dim3(8, 16), 256, SM1>>>(
        pOPhi, pOPlo,
        pWh + 3 * wstep, pWh + 3 * wstep, pWh + 3 * wstep,
        (float*)d_out, bc, 16);
}

// round 6
// speedup vs baseline: 4.0486x; 1.1763x over previous
#include <cuda_runtime.h>
#include <cuda_fp16.h>
#include <stdint.h>
#include <math.h>

#define Bb 4
#define Ss 2048
#define Dd 1024
#define Hh 16
#define Nn 256
#define DDd 64

// ---------------- scratch (device globals; no allocation allowed) ----------
__device__ __half g_U[9216 * 1024];          // pooled GEMM A fp16 [x][d][b][t] x K
__device__ float g_G[9216 * 1024];           // projection GEMM outputs (fp32)
__device__ __half g_Wh[4 * 1024 * 1024];     // transposed weights [N,K] fp16 (q,k,v,c)
__device__ float g_pool[3 * Bb * Hh * Nn * DDd];  // [x][b][h][t][dd]
__device__ float g_attn[Bb * Hh * Nn * DDd];      // [b][h][t][dd]
__device__ __half g_OP[1024 * 1024];         // up-proj output fp16 [b*t][c]

// ---------------- PTX helpers ----------------------------------------------
static __device__ __forceinline__ uint32_t smem_u32(const void* p) {
    uint32_t r;
    asm("{ .reg .u64 t; cvta.to.shared.u64 t, %1; cvt.u32.u64 %0, t; }" : "=r"(r) : "l"(p));
    return r;
}
static __device__ __forceinline__ void cp16(uint32_t dst, const void* src) {
    asm volatile("cp.async.cg.shared.global [%0], [%1], 16;" :: "r"(dst), "l"(src));
}
#define CP_COMMIT() asm volatile("cp.async.commit_group;" ::: "memory")
#define CP_WAIT1()  asm volatile("cp.async.wait_group 1;" ::: "memory")

static __device__ __forceinline__ void ldsm_x4(uint32_t* r, uint32_t addr) {
    asm volatile("ldmatrix.sync.aligned.m8n8.x4.shared.b16 {%0,%1,%2,%3}, [%4];"
                 : "=r"(r[0]), "=r"(r[1]), "=r"(r[2]), "=r"(r[3]) : "r"(addr));
}
static __device__ __forceinline__ void mma_f16(float* c, const uint32_t* a, const uint32_t* b) {
    asm volatile(
        "mma.sync.aligned.m16n8k16.row.col.f32.f16.f16.f32 "
        "{%0,%1,%2,%3}, {%4,%5,%6,%7}, {%8,%9}, {%0,%1,%2,%3};"
        : "+f"(c[0]), "+f"(c[1]), "+f"(c[2]), "+f"(c[3])
        : "r"(a[0]), "r"(a[1]), "r"(a[2]), "r"(a[3]), "r"(b[0]), "r"(b[1]));
}

// ---------------------------------------------------------------------------
// Pool kernel: pooled window sums for the 3 conv-tap-shifted variants of each
// input (q,k,v). Writes fp16 GEMM-A rows: row = ((x*3+d)*Bb+b)*Nn + t.
// ---------------------------------------------------------------------------
__global__ void __launch_bounds__(256) pool_kernel(const float* __restrict__ q,
                                                   const float* __restrict__ k,
                                                   const float* __restrict__ v) {
    const int t = blockIdx.x, b = blockIdx.y, x = blockIdx.z;
    const float* src = (x == 0) ? q : ((x == 1) ? k : v);
    const int base = 8 * t - 9;
    const int jlo = (8 * t - 7 > 0) ? (8 * t - 7) : 0;

    for (int c = threadIdx.x; c < Dd; c += 256) {
        float vv[10];
        #pragma unroll
        for (int kk = 0; kk < 10; kk++) {
            int i = base + kk;
            vv[kk] = (i >= 0) ? src[((size_t)b * Ss + i) * Dd + c] : 0.0f;
        }
        float s[3] = {0.f, 0.f, 0.f};
        for (int j = jlo; j <= 8 * t; j++) {
            int jj = j - base;
            s[0] += vv[jj - 2];
            s[1] += vv[jj - 1];
            s[2] += vv[jj - 0];
        }
        #pragma unroll
        for (int d = 0; d < 3; d++) {
            size_t row = (((size_t)(x * 3 + d)) * Bb + b) * Nn + t;
            g_U[row * Dd + c] = __float2half_rn(s[d]);
        }
    }
}

// ---------------------------------------------------------------------------
// Weight prep: transpose W [K,N] -> [N,K], round to fp16.
// ---------------------------------------------------------------------------
__global__ void __launch_bounds__(256) wprep_kernel(const float* __restrict__ W0,
                                                    const float* __restrict__ W1,
                                                    const float* __restrict__ W2,
                                                    const float* __restrict__ W3) {
    const int z = blockIdx.z;
    const float* W = (z == 0) ? W0 : ((z == 1) ? W1 : ((z == 2) ? W2 : W3));
    __half* Oh = g_Wh + (size_t)z * 1024 * 1024;
    __shared__ float tile[32][33];
    const int n0 = blockIdx.x * 32, k0 = blockIdx.y * 32;
    const int tx = threadIdx.x & 31, ty = threadIdx.x >> 5;
    #pragma unroll
    for (int j = 0; j < 4; j++)
        tile[ty + j * 8][tx] = W[(size_t)(k0 + ty + j * 8) * 1024 + n0 + tx];
    __syncthreads();
    #pragma unroll
    for (int j = 0; j < 4; j++) {
        float val = tile[tx][ty + j * 8];
        Oh[(size_t)(n0 + ty + j * 8) * 1024 + k0 + tx] = __float2half_rn(val);
    }
}

// ---------------------------------------------------------------------------
// HMMA fp16 GEMM: C[M,1024] = A @ B^T, A,B fp16, fp32 accumulate.
// CTA tile (64*MI) x 128, 3-stage cp.async pipeline (K-step 32), 8 warps
// (4 in M x 2 in N). SMEM rows padded to 80B -> conflict-free ldmatrix.
// 2 CTAs/SM. BCAST: epilogue writes each row to 8 broadcast rows of d_out.
// ---------------------------------------------------------------------------
#define BROWS 128

template <int MI, int BCAST>
__global__ void __launch_bounds__(256, 2) gemm_tc(
        const __half* __restrict__ A,
        const __half* __restrict__ B0, const __half* __restrict__ B1,
        const __half* __restrict__ B2,
        float* __restrict__ C, const float* __restrict__ bias, int mblocks_per_x) {
    constexpr int CTAM = 64 * MI;
    constexpr int ASZ = CTAM * 80;
    constexpr int BSZ = BROWS * 80;
    constexpr int STAGE = ASZ + BSZ;

    extern __shared__ char dsm[];
    const uint32_t sbase = smem_u32(dsm);
    const int tid = threadIdx.x;
    const int wid = tid >> 5, lane = tid & 31;
    const int bn = blockIdx.x, bm = blockIdx.y;
    const int x = bm / mblocks_per_x;
    const __half* Bh = (x == 0) ? B0 : ((x == 1) ? B1 : B2);

    const int warpM = wid >> 1;          // 0..3
    const int warpN = wid & 1;           // 0..1
    const uint32_t aOff = (uint32_t)((warpM * 16 * MI + (lane & 15)) * 80 + (lane >> 4) * 16);
    const uint32_t bOff = (uint32_t)(ASZ +
        (warpN * 64 + ((lane >> 4) & 1) * 8 + (lane & 7)) * 80 + ((lane >> 3) & 1) * 16);

    float acc[MI][8][4];
    #pragma unroll
    for (int mi = 0; mi < MI; mi++)
        #pragma unroll
        for (int ni = 0; ni < 8; ni++)
            #pragma unroll
            for (int j = 0; j < 4; j++) acc[mi][ni][j] = 0.f;

    auto load_chunk = [&](int ch, int st) {
        const uint32_t bb = sbase + st * STAGE;
        const int kof = ch * 32;
        #pragma unroll
        for (int it = 0; it < MI; it++) {   // A: CTAM rows * 4 cp16 / 256 thr
            int idx = tid + it * 256;
            int r = idx >> 2, qq = idx & 3;
            uint32_t dst = bb + r * 80 + qq * 16;
            size_t g = (size_t)(bm * CTAM + r) * 1024 + kof + qq * 8;
            cp16(dst, A + g);
        }
        #pragma unroll
        for (int it = 0; it < 2; it++) {    // B: 128 rows * 4 cp16 / 256 thr
            int idx = tid + it * 256;
            int r = idx >> 2, qq = idx & 3;
            uint32_t dst = bb + ASZ + r * 80 + qq * 16;
            size_t g = (size_t)(bn * BROWS + r) * 1024 + kof + qq * 8;
            cp16(dst, Bh + g);
        }
        CP_COMMIT();
    };

    // Prologue: fill 2 of 3 stages
    load_chunk(0, 0);
    load_chunk(1, 1);

    for (int i = 0; i < 32; i++) {
        CP_WAIT1();              // chunk i resident (<=1 group still in flight)
        __syncthreads();         // all warps done with chunk i-1 before overwrite
        const uint32_t bb = sbase + (i % 3) * STAGE;
        #pragma unroll
        for (int kk = 0; kk < 2; kk++) {
            uint32_t ah[MI][4];
            #pragma unroll
            for (int mi = 0; mi < MI; mi++)
                ldsm_x4(ah[mi], bb + aOff + mi * 16 * 80 + kk * 32);
            #pragma unroll
            for (int p = 0; p < 4; p++) {   // 4 n-pairs = 8 n8 tiles
                uint32_t b4[4];
                ldsm_x4(b4, bb + bOff + p * 16 * 80 + kk * 32);
                #pragma unroll
                for (int mi = 0; mi < MI; mi++) {
                    mma_f16(acc[mi][2 * p],     ah[mi], b4);
                    mma_f16(acc[mi][2 * p + 1], ah[mi], b4 + 2);
                }
            }
        }
        if (i + 2 < 32) load_chunk(i + 2, (i + 2) % 3);
        else CP_COMMIT();        // keep group count uniform for wait_group
    }

    // Epilogue
    const int row0 = bm * CTAM + warpM * 16 * MI + (lane >> 2);
    const int col0 = bn * 128 + warpN * 64 + (lane & 3) * 2;
    #pragma unroll
    for (int mi = 0; mi < MI; mi++) {
        #pragma unroll
        for (int ni = 0; ni < 8; ni++) {
            int r = row0 + mi * 16;
            int c = col0 + ni * 8;
            float b0 = 0.f, b1 = 0.f;
            if (bias) { b0 = bias[c]; b1 = bias[c + 1]; }
            float2 v0 = make_float2(acc[mi][ni][0] + b0, acc[mi][ni][1] + b1);
            float2 v1 = make_float2(acc[mi][ni][2] + b0, acc[mi][ni][3] + b1);
            if (BCAST) {
                // r in [0,1024): b = r>>8, t = r&255 -> out rows b*2048 + 8t + rep
                int rb = r >> 8, rt = r & 255;
                float* o0 = C + ((size_t)rb * Ss + rt * 8) * 1024 + c;
                int r8 = r + 8;
                int rb2 = r8 >> 8, rt2 = r8 & 255;
                float* o1 = C + ((size_t)rb2 * Ss + rt2 * 8) * 1024 + c;
                #pragma unroll
                for (int rep = 0; rep < 8; rep++) {
                    *(float2*)(o0 + rep * 1024) = v0;
                    *(float2*)(o1 + rep * 1024) = v1;
                }
            } else {
                *(float2*)&C[(size_t)r * 1024 + c] = v0;
                *(float2*)&C[(size_t)(r + 8) * 1024 + c] = v1;
            }
        }
    }
}

// ---------------------------------------------------------------------------
// Combine: fold conv weights + biases + norm scale + /8 into pooled q/k/v.
// ---------------------------------------------------------------------------
__global__ void __launch_bounds__(256) combine_kernel(
        const float* __restrict__ wcq, const float* __restrict__ bcq, const float* __restrict__ bq,
        const float* __restrict__ wck, const float* __restrict__ bck, const float* __restrict__ bk,
        const float* __restrict__ wcv, const float* __restrict__ bcv, const float* __restrict__ bv) {
    const int t = blockIdx.x, b = blockIdx.y, x = blockIdx.z;
    const float* wc = (x == 0) ? wcq : ((x == 1) ? wck : wcv);
    const float* bc = (x == 0) ? bcq : ((x == 1) ? bck : bcv);
    const float* bd = (x == 0) ? bq  : ((x == 1) ? bk  : bv);
    const float scale = (x == 2) ? 1.0f : 0.35355339059327379f;  // 64^-0.25

    float cJ, c0, c1, c2;
    if (t == 0)      { cJ = 1.f; c0 = 0.f; c1 = 0.f; c2 = 1.f; }
    else if (t == 1) { cJ = 8.f; c0 = 7.f; c1 = 8.f; c2 = 8.f; }
    else             { cJ = 8.f; c0 = 8.f; c1 = 8.f; c2 = 8.f; }

    const size_t ds = (size_t)Bb * Nn * Dd;
    const size_t base0 = ((((size_t)x * 3 + 0) * Bb + b) * Nn + t) * Dd;

    for (int c = threadIdx.x; c < Dd; c += 256) {
        float G0 = g_G[base0 + c];
        float G1 = g_G[base0 + ds + c];
        float G2 = g_G[base0 + 2 * ds + c];
        float bdc = bd[c];
        float val = cJ * bc[c] + scale * (wc[c]          * (G0 + c0 * bdc) +
                                          wc[Dd + c]     * (G1 + c1 * bdc) +
                                          wc[2 * Dd + c] * (G2 + c2 * bdc));
        val *= 0.125f;
        int h = c >> 6, dd = c & 63;
        g_pool[((((size_t)x * Bb + b) * Hh + h) * Nn + t) * DDd + dd] = val;
    }
}

// ---------------------------------------------------------------------------
// Attention per (b,h): thread i = query row i, online softmax, causal skip.
// ---------------------------------------------------------------------------
__global__ void __launch_bounds__(256) attn_kernel() {
    const int bh = blockIdx.x;
    __shared__ float sK[64][DDd];
    __shared__ float sV[64][DDd];
    const float* qp = g_pool + ((size_t)0 * Bb * Hh + bh) * Nn * DDd;
    const float* kp = g_pool + ((size_t)1 * Bb * Hh + bh) * Nn * DDd;
    const float* vp = g_pool + ((size_t)2 * Bb * Hh + bh) * Nn * DDd;
    const int i = threadIdx.x;

    float qreg[DDd];
    #pragma unroll
    for (int d = 0; d < DDd; d++) qreg[d] = qp[(size_t)i * DDd + d];

    float mi = -1e30f, li = 0.f;
    float acc[DDd];
    #pragma unroll
    for (int d = 0; d < DDd; d++) acc[d] = 0.f;

    for (int kt = 0; kt < Nn; kt += 64) {
        for (int idx = threadIdx.x; idx < 64 * DDd / 4; idx += 256) {
            ((float4*)&sK[0][0])[idx] = ((const float4*)(kp + (size_t)kt * DDd))[idx];
            ((float4*)&sV[0][0])[idx] = ((const float4*)(vp + (size_t)kt * DDd))[idx];
        }
        __syncthreads();
        int mmax = i - kt; if (mmax > 63) mmax = 63;
        for (int m = 0; m <= mmax; m++) {
            float d0 = 0.f, d1 = 0.f, d2 = 0.f, d3 = 0.f;
            #pragma unroll
            for (int d = 0; d < DDd; d += 4) {
                d0 += qreg[d + 0] * sK[m][d + 0];
                d1 += qreg[d + 1] * sK[m][d + 1];
                d2 += qreg[d + 2] * sK[m][d + 2];
                d3 += qreg[d + 3] * sK[m][d + 3];
            }
            float dot = (d0 + d1) + (d2 + d3);
            if (dot > mi) {
                float f = __expf(mi - dot);
                li *= f;
                #pragma unroll
                for (int d = 0; d < DDd; d++) acc[d] *= f;
                mi = dot;
            }
            float p = __expf(dot - mi);
            li += p;
            #pragma unroll
            for (int d = 0; d < DDd; d++) acc[d] += p * sV[m][d];
        }
        __syncthreads();
    }

    float inv = 1.0f / li;
    float* outp = g_attn + ((size_t)bh * Nn + i) * DDd;
    #pragma unroll
    for (int d = 0; d < DDd; d++) outp[d] = acc[d] * inv;
}

// ---------------------------------------------------------------------------
// Up-projection (Wup [64,64] per head) + merge -> fp16 rows for Wc GEMM
// ---------------------------------------------------------------------------
__global__ void __launch_bounds__(256) up_kernel(const float* __restrict__ Wup,
                                                 const float* __restrict__ bup) {
    const int bt = blockIdx.x;
    const int b = bt >> 8, t = bt & 255;
    __shared__ float sW[DDd * DDd];
    __shared__ float sIn[Hh * DDd];
    for (int idx = threadIdx.x; idx < DDd * DDd; idx += 256) sW[idx] = Wup[idx];
    for (int idx = threadIdx.x; idx < Hh * DDd; idx += 256) {
        int h = idx >> 6, dd = idx & 63;
        sIn[idx] = g_attn[(((size_t)b * Hh + h) * Nn + t) * DDd + dd];
    }
    __syncthreads();
    for (int c = threadIdx.x; c < Dd; c += 256) {
        int h = c >> 6, ddp = c & 63;
        float s = bup[ddp];
        #pragma unroll
        for (int dd = 0; dd < DDd; dd++) s += sIn[h * DDd + dd] * sW[dd * DDd + ddp];
        g_OP[((size_t)b * Nn + t) * Dd + c] = __float2half_rn(s);
    }
}

// ---------------------------------------------------------------------------
extern "C" void kernel_launch(void* const* d_in, const int* in_sizes, int n_in,
                              void* d_out, int out_size) {
    const float* q   = (const float*)d_in[0];
    const float* k   = (const float*)d_in[1];
    const float* v   = (const float*)d_in[2];
    const float* Wq  = (const float*)d_in[3];
    const float* bq  = (const float*)d_in[4];
    const float* Wk  = (const float*)d_in[5];
    const float* bk  = (const float*)d_in[6];
    const float* Wv  = (const float*)d_in[7];
    const float* bv  = (const float*)d_in[8];
    const float* Wup = (const float*)d_in[9];
    const float* bup = (const float*)d_in[10];
    const float* Wc  = (const float*)d_in[11];
    const float* bc  = (const float*)d_in[12];
    const float* wcq = (const float*)d_in[13];
    const float* bcq = (const float*)d_in[14];
    const float* wck = (const float*)d_in[15];
    const float* bck = (const float*)d_in[16];
    const float* wcv = (const float*)d_in[17];
    const float* bcv = (const float*)d_in[18];

    __half *pU, *pWh, *pOP;
    float *pG;
    cudaGetSymbolAddress((void**)&pU, g_U);
    cudaGetSymbolAddress((void**)&pWh, g_Wh);
    cudaGetSymbolAddress((void**)&pOP, g_OP);
    cudaGetSymbolAddress((void**)&pG, g_G);

    // smem: MI=2: 3 * (128*80 + 128*80) = 61440 ; MI=1: 3 * (64*80 + 128*80) = 46080
    const int SM2 = 3 * (128 * 80 + 128 * 80);
    const int SM1 = 3 * (64 * 80 + 128 * 80);
    cudaFuncSetAttribute((const void*)gemm_tc<2, 0>, cudaFuncAttributeMaxDynamicSharedMemorySize, SM2);
    cudaFuncSetAttribute((const void*)gemm_tc<1, 1>, cudaFuncAttributeMaxDynamicSharedMemorySize, SM1);

    // 1. Weight transpose + fp16 round (Wq,Wk,Wv,Wc)
    wprep_kernel<<<dim3(32, 32, 4), 256>>>(Wq, Wk, Wv, Wc);

    // 2. Pooled GEMM inputs (dw-conv decomposition + causal pool), fp16
    pool_kernel<<<dim3(Nn, Bb, 3), 256>>>(q, k, v);

    // 3. Fused projection GEMMs: [9216,1024] @ per-x [1024,1024]^T
    const size_t wstep = (size_t)1024 * 1024;
    gemm_tc<2, 0><<<dim3(8, 72), 256, SM2>>>(
        pU, pWh + 0 * wstep, pWh + 1 * wstep, pWh + 2 * wstep,
        pG, nullptr, 24);

    // 4. Combine conv weights/biases/scale -> pooled q/k/v
    combine_kernel<<<dim3(Nn, Bb, 3), 256>>>(wcq, bcq, bq, wck, bck, bk, wcv, bcv, bv);

    // 5. Causal attention over pooled tokens
    attn_kernel<<<Bb * Hh, 256>>>();

    // 6. Per-head Wup + merge heads -> fp16
    up_kernel<<<Bb * Nn, 256>>>(Wup, bup);

    // 7. Final dense Wc (+bias), epilogue broadcasts each row to 8 seq positions
    gemm_tc<1, 1><<<dim3(8, 16), 256, SM1>>>(
        pOP, pWh + 3 * wstep, pWh + 3 * wstep, pWh + 3 * wstep,
        (float*)d_out, bc, 16);
}